// round 1
// baseline (speedup 1.0000x reference)
#include <cuda_runtime.h>
#include <math.h>

#define NBLK 1184
#define TPB  256

// Per-block partial sums of the 55 unique Gram entries.
__device__ float g_part[NBLK][55];

__device__ __forceinline__ constexpr int tri_idx(int i, int j) {
    return i * 10 - (i * (i + 1)) / 2 + j;   // i <= j
}

// ---------------------------------------------------------------------------
// Kernel 1: deterministic Gram partial reduction.
// Each thread owns a fixed set of 2-row units (80B = 5 aligned float4 loads).
// ---------------------------------------------------------------------------
__global__ __launch_bounds__(TPB, 2) void gram_kernel(const float* __restrict__ x,
                                                      int units, int nrows)
{
    const float4* __restrict__ xv = (const float4*)x;
    float acc[55];
#pragma unroll
    for (int k = 0; k < 55; k++) acc[k] = 0.f;

    int tid = blockIdx.x * TPB + threadIdx.x;
    const int stride = NBLK * TPB;
    for (int p = tid; p < units; p += stride) {
        float v[20];
        int base = 5 * p;
        float4 q;
        q = xv[base + 0]; v[0]  = q.x; v[1]  = q.y; v[2]  = q.z; v[3]  = q.w;
        q = xv[base + 1]; v[4]  = q.x; v[5]  = q.y; v[6]  = q.z; v[7]  = q.w;
        q = xv[base + 2]; v[8]  = q.x; v[9]  = q.y; v[10] = q.z; v[11] = q.w;
        q = xv[base + 3]; v[12] = q.x; v[13] = q.y; v[14] = q.z; v[15] = q.w;
        q = xv[base + 4]; v[16] = q.x; v[17] = q.y; v[18] = q.z; v[19] = q.w;
#pragma unroll
        for (int i = 0; i < 10; i++)
#pragma unroll
            for (int j = i; j < 10; j++) {
                acc[tri_idx(i, j)] = fmaf(v[i],      v[j],      acc[tri_idx(i, j)]);
                acc[tri_idx(i, j)] = fmaf(v[10 + i], v[10 + j], acc[tri_idx(i, j)]);
            }
    }
    // Odd trailing row (not hit for N=4M, kept for shape robustness).
    if (tid == 0 && (nrows & 1)) {
        const float* last = x + (size_t)(nrows - 1) * 10;
        float v[10];
#pragma unroll
        for (int i = 0; i < 10; i++) v[i] = last[i];
#pragma unroll
        for (int i = 0; i < 10; i++)
#pragma unroll
            for (int j = i; j < 10; j++)
                acc[tri_idx(i, j)] = fmaf(v[i], v[j], acc[tri_idx(i, j)]);
    }

    // Deterministic warp shuffle tree reduce per entry.
#pragma unroll
    for (int k = 0; k < 55; k++) {
#pragma unroll
        for (int off = 16; off > 0; off >>= 1)
            acc[k] += __shfl_down_sync(0xffffffffu, acc[k], off);
    }
    __shared__ float red[TPB / 32][55];
    int lane = threadIdx.x & 31, wid = threadIdx.x >> 5;
    if (lane == 0) {
#pragma unroll
        for (int k = 0; k < 55; k++) red[wid][k] = acc[k];
    }
    __syncthreads();
    if (threadIdx.x < 55) {
        float s = 0.f;
#pragma unroll
        for (int w = 0; w < TPB / 32; w++) s += red[w][threadIdx.x];
        g_part[blockIdx.x][threadIdx.x] = s;
    }
}

// ---------------------------------------------------------------------------
// LAPACK-faithful fp32 helpers (ssyevd path: ssytrd -> ssteqr)
// ---------------------------------------------------------------------------
__device__ __forceinline__ float signf_(float a, float b) {
    return b >= 0.f ? fabsf(a) : -fabsf(a);
}
__device__ __forceinline__ float slapy2_(float xx, float yy) {
    float xa = fabsf(xx), ya = fabsf(yy);
    float w = fmaxf(xa, ya), zz = fminf(xa, ya);
    if (zz == 0.f) return w;
    float t = zz / w;
    return w * sqrtf(1.f + t * t);
}
// LAPACK >= 3.10 slartg (unscaled path; magnitudes here are benign)
__device__ __forceinline__ void slartg_(float f, float g, float* cs, float* sn, float* r) {
    if (g == 0.f)      { *cs = 1.f; *sn = 0.f; *r = f; }
    else if (f == 0.f) { *cs = 0.f; *sn = (g >= 0.f ? 1.f : -1.f); *r = fabsf(g); }
    else {
        float d  = sqrtf(f * f + g * g);
        *cs = fabsf(f) / d;
        float rr = (f >= 0.f ? d : -d);
        *r = rr;
        *sn = g / rr;
    }
}
__device__ void slaev2_(float a, float b, float cc,
                        float* rt1, float* rt2, float* cs1o, float* sn1o) {
    float sm = a + cc, df = a - cc;
    float adf = fabsf(df), tb = b + b, ab = fabsf(tb);
    float acmx, acmn;
    if (fabsf(a) > fabsf(cc)) { acmx = a;  acmn = cc; }
    else                      { acmx = cc; acmn = a;  }
    float rt;
    if (adf > ab)      { float t = ab / adf;  rt = adf * sqrtf(1.f + t * t); }
    else if (adf < ab) { float t = adf / ab;  rt = ab  * sqrtf(1.f + t * t); }
    else               rt = ab * sqrtf(2.f);
    int sgn1;
    if (sm < 0.f)      { *rt1 = 0.5f * (sm - rt); sgn1 = -1;
                         *rt2 = (acmx / *rt1) * acmn - (b / *rt1) * b; }
    else if (sm > 0.f) { *rt1 = 0.5f * (sm + rt); sgn1 = 1;
                         *rt2 = (acmx / *rt1) * acmn - (b / *rt1) * b; }
    else               { *rt1 = 0.5f * rt; *rt2 = -0.5f * rt; sgn1 = 1; }
    float cs; int sgn2;
    if (df >= 0.f) { cs = df + rt; sgn2 = 1; }
    else           { cs = df - rt; sgn2 = -1; }
    float acs = fabsf(cs), c1, s1;
    if (acs > ab) { float ct = -tb / cs; s1 = 1.f / sqrtf(1.f + ct * ct); c1 = ct * s1; }
    else {
        if (ab == 0.f) { c1 = 1.f; s1 = 0.f; }
        else { float tn = -cs / tb; c1 = 1.f / sqrtf(1.f + tn * tn); s1 = tn * c1; }
    }
    if (sgn1 == sgn2) { float t = c1; c1 = -s1; s1 = t; }
    *cs1o = c1; *sn1o = s1;
}

// ---------------------------------------------------------------------------
// Kernel 2: deterministic double reduce -> fp32 gram -> LAPACK-clone
// eigensolver (ssytrd + sorgtr-equivalent + ssteqr + ascending sort) -> MLP.
// ---------------------------------------------------------------------------
__global__ void finish_kernel(const float* __restrict__ W1, const float* __restrict__ b1,
                              const float* __restrict__ W2, const float* __restrict__ b2,
                              float* __restrict__ out)
{
    __shared__ float A[10][10];
    __shared__ float Zs[10][10];
    int t = threadIdx.x;
    if (t < 55) {
        double s0 = 0.0, s1 = 0.0, s2 = 0.0, s3 = 0.0;
        for (int b4 = 0; b4 < NBLK; b4 += 4) {   // NBLK % 4 == 0
            s0 += (double)g_part[b4 + 0][t];
            s1 += (double)g_part[b4 + 1][t];
            s2 += (double)g_part[b4 + 2][t];
            s3 += (double)g_part[b4 + 3][t];
        }
        double s = (s0 + s1) + (s2 + s3);
        int i = 0, rem = t;
        while (rem >= 10 - i) { rem -= 10 - i; i++; }
        int j = i + rem;
        float fv = (float)s;
        A[i][j] = fv; A[j][i] = fv;
    }
    __syncthreads();
    if (t != 0) return;

    // ---- ssytd2 (UPLO='L') --------------------------------------------------
    float dd[10], ee[10], tau9[9], wc[10], ws[10];
    for (int ii = 0; ii < 9; ii++) {
        float alpha = A[ii + 1][ii];
        float xn2 = 0.f;
        for (int r = ii + 2; r < 10; r++) xn2 += A[r][ii] * A[r][ii];
        float xnorm = sqrtf(xn2);
        float taui;
        if (xnorm == 0.f) {
            taui = 0.f;
            ee[ii] = alpha;
        } else {
            float beta = -signf_(slapy2_(alpha, xnorm), alpha);
            taui = (beta - alpha) / beta;
            float sc = 1.f / (alpha - beta);
            for (int r = ii + 2; r < 10; r++) A[r][ii] *= sc;
            ee[ii] = beta;
            A[ii + 1][ii] = 1.f;
            float w[10];
            for (int r = ii + 1; r < 10; r++) {
                float s = 0.f;
                for (int c = ii + 1; c < 10; c++) {
                    float av = (r >= c) ? A[r][c] : A[c][r];   // lower storage
                    s += av * A[c][ii];
                }
                w[r] = taui * s;
            }
            float dot = 0.f;
            for (int r = ii + 1; r < 10; r++) dot += w[r] * A[r][ii];
            float alw = -0.5f * taui * dot;
            for (int r = ii + 1; r < 10; r++) w[r] += alw * A[r][ii];
            for (int r = ii + 1; r < 10; r++)
                for (int c = ii + 1; c <= r; c++)
                    A[r][c] -= A[r][ii] * w[c] + w[r] * A[c][ii];
            A[ii + 1][ii] = ee[ii];
        }
        tau9[ii] = taui;
    }
    for (int k = 0; k < 10; k++) dd[k] = A[k][k];

    // ---- Q = H(1)..H(n-1) (dorgtr 'L' equivalent) ---------------------------
    for (int r = 0; r < 10; r++)
        for (int c = 0; c < 10; c++) Zs[r][c] = (r == c) ? 1.f : 0.f;
    for (int ii = 8; ii >= 0; ii--) {
        float taui = tau9[ii];
        if (taui == 0.f) continue;
        for (int j = 0; j < 10; j++) {
            float s = Zs[ii + 1][j];
            for (int r = ii + 2; r < 10; r++) s += A[r][ii] * Zs[r][j];
            s *= taui;
            Zs[ii + 1][j] -= s;
            for (int r = ii + 2; r < 10; r++) Zs[r][j] -= A[r][ii] * s;
        }
    }

    // ---- ssteqr ('V'), 1-based macros to mirror LAPACK ---------------------
#define D1(k)   dd[(k) - 1]
#define E1(k)   ee[(k) - 1]
#define ZV(i,k) Zs[i][(k) - 1]
#define WC1(k)  wc[(k) - 1]
#define WS1(k)  ws[(k) - 1]
    const float EPS    = 5.9604645e-08f;   // slamch('E') for fp32
    const float EPS2   = EPS * EPS;
    const float SAFMIN = 1.1754944e-38f;
    int n = 10, nmaxit = n * 30, jtot = 0;
    int l1 = 1, l = 0, lsv, lend, lendsv, m;
    float p, g, r, c, s, f, b, rt1, rt2;

L10:
    if (l1 > n) goto L160;
    if (l1 > 1) E1(l1 - 1) = 0.f;
    if (l1 <= n - 1) {
        for (m = l1; m <= n - 1; m++) {
            float tst = fabsf(E1(m));
            if (tst == 0.f) goto L30;
            if (tst <= (sqrtf(fabsf(D1(m))) * sqrtf(fabsf(D1(m + 1)))) * EPS) {
                E1(m) = 0.f; goto L30;
            }
        }
    }
    m = n;
L30:
    l = l1; lsv = l; lend = m; lendsv = lend; l1 = m + 1;
    if (lend == l) goto L10;
    if (fabsf(D1(lend)) < fabsf(D1(l))) { lend = lsv; l = lendsv; }
    if (lend > l) goto L40; else goto L90;

    // ============ QL iteration ============
L40:
    if (l != lend) {
        int found = 0;
        for (m = l; m <= lend - 1; m++) {
            float tst = E1(m) * E1(m);
            if (tst <= EPS2 * fabsf(D1(m)) * fabsf(D1(m + 1)) + SAFMIN) { found = 1; break; }
        }
        if (!found) m = lend;
    } else m = lend;
    if (m < lend) E1(m) = 0.f;
    p = D1(l);
    if (m == l) goto L80;
    if (m == l + 1) {
        slaev2_(D1(l), E1(l), D1(l + 1), &rt1, &rt2, &c, &s);
        for (int i = 0; i < 10; i++) {
            float tmp = ZV(i, l + 1);
            ZV(i, l + 1) = c * tmp - s * ZV(i, l);
            ZV(i, l)     = s * tmp + c * ZV(i, l);
        }
        D1(l) = rt1; D1(l + 1) = rt2; E1(l) = 0.f;
        l += 2;
        if (l <= lend) goto L40;
        goto L140;
    }
    if (jtot == nmaxit) goto L140;
    jtot++;
    g = (D1(l + 1) - p) / (2.f * E1(l));
    r = slapy2_(g, 1.f);
    g = D1(m) - p + E1(l) / (g + signf_(r, g));
    s = 1.f; c = 1.f; p = 0.f;
    for (int i = m - 1; i >= l; i--) {
        f = s * E1(i); b = c * E1(i);
        slartg_(g, f, &c, &s, &r);
        if (i != m - 1) E1(i + 1) = r;
        g = D1(i + 1) - p;
        r = (D1(i) - g) * s + 2.f * c * b;
        p = s * r;
        D1(i + 1) = g + p;
        g = c * r - b;
        WC1(i) = c; WS1(i) = -s;
    }
    for (int j = m - 1; j >= l; j--) {            // slasr 'R','V','B'
        float ct = WC1(j), st = WS1(j);
        for (int i = 0; i < 10; i++) {
            float tmp = ZV(i, j + 1);
            ZV(i, j + 1) = ct * tmp - st * ZV(i, j);
            ZV(i, j)     = st * tmp + ct * ZV(i, j);
        }
    }
    D1(l) -= p; E1(l) = g;
    goto L40;
L80:
    D1(l) = p;
    l++;
    if (l <= lend) goto L40;
    goto L140;

    // ============ QR iteration ============
L90:
    if (l != lend) {
        int found = 0;
        for (m = l; m >= lend + 1; m--) {
            float tst = E1(m - 1) * E1(m - 1);
            if (tst <= EPS2 * fabsf(D1(m)) * fabsf(D1(m - 1)) + SAFMIN) { found = 1; break; }
        }
        if (!found) m = lend;
    } else m = lend;
    if (m > lend) E1(m - 1) = 0.f;
    p = D1(l);
    if (m == l) goto L130;
    if (m == l - 1) {
        slaev2_(D1(l - 1), E1(l - 1), D1(l), &rt1, &rt2, &c, &s);
        for (int i = 0; i < 10; i++) {            // slasr 'R','V','F', 2 cols
            float tmp = ZV(i, l);
            ZV(i, l)     = c * tmp - s * ZV(i, l - 1);
            ZV(i, l - 1) = s * tmp + c * ZV(i, l - 1);
        }
        D1(l - 1) = rt1; D1(l) = rt2; E1(l - 1) = 0.f;
        l -= 2;
        if (l >= lend) goto L90;
        goto L140;
    }
    if (jtot == nmaxit) goto L140;
    jtot++;
    g = (D1(l - 1) - p) / (2.f * E1(l - 1));
    r = slapy2_(g, 1.f);
    g = D1(m) - p + E1(l - 1) / (g + signf_(r, g));
    s = 1.f; c = 1.f; p = 0.f;
    for (int i = m; i <= l - 1; i++) {
        f = s * E1(i); b = c * E1(i);
        slartg_(g, f, &c, &s, &r);
        if (i != m) E1(i - 1) = r;
        g = D1(i) - p;
        r = (D1(i + 1) - g) * s + 2.f * c * b;
        p = s * r;
        D1(i) = g + p;
        g = c * r - b;
        WC1(i) = c; WS1(i) = s;
    }
    for (int j = m; j <= l - 1; j++) {            // slasr 'R','V','F'
        float ct = WC1(j), st = WS1(j);
        for (int i = 0; i < 10; i++) {
            float tmp = ZV(i, j + 1);
            ZV(i, j + 1) = ct * tmp - st * ZV(i, j);
            ZV(i, j)     = st * tmp + ct * ZV(i, j);
        }
    }
    D1(l) -= p; E1(l - 1) = g;
    goto L90;
L130:
    D1(l) = p;
    l--;
    if (l >= lend) goto L90;
    goto L140;

L140:
    if (jtot < nmaxit) goto L10;
    goto L160;

L160:
    // Ascending selection sort with column swaps (exactly LAPACK's).
    for (int ii2 = 2; ii2 <= n; ii2++) {
        int i = ii2 - 1, k = i;
        float pp = D1(i);
        for (int j = ii2; j <= n; j++)
            if (D1(j) < pp) { k = j; pp = D1(j); }
        if (k != i) {
            D1(k) = D1(i); D1(i) = pp;
            for (int rr = 0; rr < 10; rr++) {
                float tmp = ZV(rr, i); ZV(rr, i) = ZV(rr, k); ZV(rr, k) = tmp;
            }
        }
    }

    // ---- MLP: y = relu(w @ W1.T + b1) @ W2.T + b2; out = 0.5*(sigmoid+1) ---
    for (int i = 0; i < 10; i++) {
        float y2 = b2[0];
        for (int h = 0; h < 16; h++) {
            float a1 = b1[h];
            for (int j = 0; j < 10; j++) a1 = fmaf(Zs[i][j], W1[h * 10 + j], a1);
            a1 = fmaxf(a1, 0.f);
            y2 = fmaf(a1, W2[h], y2);
        }
        out[i] = 0.5f * (1.f / (1.f + expf(-y2)) + 1.f);
    }
#undef D1
#undef E1
#undef ZV
#undef WC1
#undef WS1
}

extern "C" void kernel_launch(void* const* d_in, const int* in_sizes, int n_in,
                              void* d_out, int out_size)
{
    const float* x  = (const float*)d_in[0];
    const float* W1 = (const float*)d_in[1];
    const float* b1 = (const float*)d_in[2];
    const float* W2 = (const float*)d_in[3];
    const float* b2 = (const float*)d_in[4];
    int nrows = in_sizes[0] / 10;
    int units = nrows / 2;
    gram_kernel<<<NBLK, TPB>>>(x, units, nrows);
    finish_kernel<<<1, 64>>>(W1, b1, W2, b2, (float*)d_out);
}

// round 2
// speedup vs baseline: 1.1931x; 1.1931x over previous
#include <cuda_runtime.h>
#include <math.h>

#define NBLK 1184
#define TPB  256

// Per-block partial sums of the 55 unique Gram entries.
__device__ float g_part[NBLK][55];

__device__ __forceinline__ constexpr int tri_idx(int i, int j) {
    return i * 10 - (i * (i + 1)) / 2 + j;   // i <= j
}

// ---------------------------------------------------------------------------
// Kernel 1: deterministic Gram partial reduction (unchanged from R1; ~30us,
// near the HBM floor for 160MB).
// ---------------------------------------------------------------------------
__global__ __launch_bounds__(TPB, 2) void gram_kernel(const float* __restrict__ x,
                                                      int units, int nrows)
{
    const float4* __restrict__ xv = (const float4*)x;
    float acc[55];
#pragma unroll
    for (int k = 0; k < 55; k++) acc[k] = 0.f;

    int tid = blockIdx.x * TPB + threadIdx.x;
    const int stride = NBLK * TPB;
    for (int p = tid; p < units; p += stride) {
        float v[20];
        int base = 5 * p;
        float4 q;
        q = xv[base + 0]; v[0]  = q.x; v[1]  = q.y; v[2]  = q.z; v[3]  = q.w;
        q = xv[base + 1]; v[4]  = q.x; v[5]  = q.y; v[6]  = q.z; v[7]  = q.w;
        q = xv[base + 2]; v[8]  = q.x; v[9]  = q.y; v[10] = q.z; v[11] = q.w;
        q = xv[base + 3]; v[12] = q.x; v[13] = q.y; v[14] = q.z; v[15] = q.w;
        q = xv[base + 4]; v[16] = q.x; v[17] = q.y; v[18] = q.z; v[19] = q.w;
#pragma unroll
        for (int i = 0; i < 10; i++)
#pragma unroll
            for (int j = i; j < 10; j++) {
                acc[tri_idx(i, j)] = fmaf(v[i],      v[j],      acc[tri_idx(i, j)]);
                acc[tri_idx(i, j)] = fmaf(v[10 + i], v[10 + j], acc[tri_idx(i, j)]);
            }
    }
    if (tid == 0 && (nrows & 1)) {
        const float* last = x + (size_t)(nrows - 1) * 10;
        float v[10];
#pragma unroll
        for (int i = 0; i < 10; i++) v[i] = last[i];
#pragma unroll
        for (int i = 0; i < 10; i++)
#pragma unroll
            for (int j = i; j < 10; j++)
                acc[tri_idx(i, j)] = fmaf(v[i], v[j], acc[tri_idx(i, j)]);
    }

#pragma unroll
    for (int k = 0; k < 55; k++) {
#pragma unroll
        for (int off = 16; off > 0; off >>= 1)
            acc[k] += __shfl_down_sync(0xffffffffu, acc[k], off);
    }
    __shared__ float red[TPB / 32][55];
    int lane = threadIdx.x & 31, wid = threadIdx.x >> 5;
    if (lane == 0) {
#pragma unroll
        for (int k = 0; k < 55; k++) red[wid][k] = acc[k];
    }
    __syncthreads();
    if (threadIdx.x < 55) {
        float s = 0.f;
#pragma unroll
        for (int w = 0; w < TPB / 32; w++) s += red[w][threadIdx.x];
        g_part[blockIdx.x][threadIdx.x] = s;
    }
}

// ---------------------------------------------------------------------------
// LAPACK-faithful fp32 helpers
// ---------------------------------------------------------------------------
__device__ __forceinline__ float signf_(float a, float b) {
    return b >= 0.f ? fabsf(a) : -fabsf(a);
}
__device__ __forceinline__ float slapy2_(float xx, float yy) {
    float xa = fabsf(xx), ya = fabsf(yy);
    float w = fmaxf(xa, ya), zz = fminf(xa, ya);
    if (zz == 0.f) return w;
    float t = zz / w;
    return w * sqrtf(1.f + t * t);
}
__device__ __forceinline__ void slartg_(float f, float g, float* cs, float* sn, float* r) {
    if (g == 0.f)      { *cs = 1.f; *sn = 0.f; *r = f; }
    else if (f == 0.f) { *cs = 0.f; *sn = (g >= 0.f ? 1.f : -1.f); *r = fabsf(g); }
    else {
        float d  = sqrtf(f * f + g * g);
        *cs = fabsf(f) / d;
        float rr = (f >= 0.f ? d : -d);
        *r = rr;
        *sn = g / rr;
    }
}
__device__ void slaev2_(float a, float b, float cc,
                        float* rt1, float* rt2, float* cs1o, float* sn1o) {
    float sm = a + cc, df = a - cc;
    float adf = fabsf(df), tb = b + b, ab = fabsf(tb);
    float acmx, acmn;
    if (fabsf(a) > fabsf(cc)) { acmx = a;  acmn = cc; }
    else                      { acmx = cc; acmn = a;  }
    float rt;
    if (adf > ab)      { float t = ab / adf;  rt = adf * sqrtf(1.f + t * t); }
    else if (adf < ab) { float t = adf / ab;  rt = ab  * sqrtf(1.f + t * t); }
    else               rt = ab * sqrtf(2.f);
    int sgn1;
    if (sm < 0.f)      { *rt1 = 0.5f * (sm - rt); sgn1 = -1;
                         *rt2 = (acmx / *rt1) * acmn - (b / *rt1) * b; }
    else if (sm > 0.f) { *rt1 = 0.5f * (sm + rt); sgn1 = 1;
                         *rt2 = (acmx / *rt1) * acmn - (b / *rt1) * b; }
    else               { *rt1 = 0.5f * rt; *rt2 = -0.5f * rt; sgn1 = 1; }
    float cs; int sgn2;
    if (df >= 0.f) { cs = df + rt; sgn2 = 1; }
    else           { cs = df - rt; sgn2 = -1; }
    float acs = fabsf(cs), c1, s1;
    if (acs > ab) { float ct = -tb / cs; s1 = 1.f / sqrtf(1.f + ct * ct); c1 = ct * s1; }
    else {
        if (ab == 0.f) { c1 = 1.f; s1 = 0.f; }
        else { float tn = -cs / tb; c1 = 1.f / sqrtf(1.f + tn * tn); s1 = tn * c1; }
    }
    if (sgn1 == sgn2) { float t = c1; c1 = -s1; s1 = t; }
    *cs1o = c1; *sn1o = s1;
}

// ---------------------------------------------------------------------------
// Kernel 2 (warp-cooperative): parallel reduce -> fp32 gram -> LAPACK-clone
// eigensolver with lanes 0-9 owning rows/columns, Z rows in registers,
// scalar driver replicated per-lane (private state, no cross-lane hazards).
// ---------------------------------------------------------------------------
__global__ void finish_kernel(const float* __restrict__ W1, const float* __restrict__ b1,
                              const float* __restrict__ W2, const float* __restrict__ b2,
                              float* __restrict__ out)
{
    __shared__ double part[55][8];
    __shared__ float A[10][10];
    __shared__ float Zsh[10][10];
    __shared__ float wsh[10];
    __shared__ float sW1[160], sb1[16], sW2[16], sb2[1];

    int t = threadIdx.x;

    // ---- preload MLP weights ----
    if (t < 160)       sW1[t]        = W1[t];
    else if (t < 176)  sb1[t - 160]  = b1[t - 160];
    else if (t < 192)  sW2[t - 176]  = W2[t - 176];
    else if (t == 192) sb2[0]        = b2[0];

    // ---- parallel deterministic double reduction: 55 entries x 8 partitions ----
    if (t < 440) {
        int e = t >> 3, q = t & 7;
        int b0 = q * (NBLK / 8);               // 148 blocks per partition
        double a0 = 0.0, a1 = 0.0, a2 = 0.0, a3 = 0.0;
        for (int b = 0; b < NBLK / 8; b += 4) {
            a0 += (double)g_part[b0 + b + 0][e];
            a1 += (double)g_part[b0 + b + 1][e];
            a2 += (double)g_part[b0 + b + 2][e];
            a3 += (double)g_part[b0 + b + 3][e];
        }
        part[e][q] = (a0 + a1) + (a2 + a3);
    }
    __syncthreads();
    if (t < 55) {
        double s = 0.0;
#pragma unroll
        for (int q = 0; q < 8; q++) s += part[t][q];   // fixed order
        int i = 0, rem = t;
        while (rem >= 10 - i) { rem -= 10 - i; i++; }
        int j = i + rem;
        float fv = (float)s;
        A[i][j] = fv; A[j][i] = fv;
    }
    __syncthreads();
    if (t >= 32) return;
    const unsigned M = 0x3ffu;
    int lane = t;
    if (lane >= 10) return;

    // =======================================================================
    // ssytd2 (UPLO='L'), lane-parallel row phases; ee/tau private per lane.
    // =======================================================================
    float eel[10], taul[9], ddl[10], wcl[10], wsl[10];
    for (int ii = 0; ii < 9; ii++) {
        __syncwarp(M);
        float alpha = A[ii + 1][ii];
        float xn2 = 0.f;
        for (int r = ii + 2; r < 10; r++) xn2 += A[r][ii] * A[r][ii];
        float xnorm = sqrtf(xn2);
        float taui;
        if (xnorm == 0.f) {
            taui = 0.f;
            eel[ii] = alpha;
        } else {
            float beta = -signf_(slapy2_(alpha, xnorm), alpha);
            taui = (beta - alpha) / beta;
            float sc = 1.f / (alpha - beta);
            eel[ii] = beta;
            __syncwarp(M);                       // all lanes done reading col ii
            if (lane >= ii + 2) A[lane][ii] *= sc;
            if (lane == ii + 1) A[ii + 1][ii] = 1.f;
            __syncwarp(M);
            // w[r] = taui * (A_sub v)[r], lane r computes its row
            if (lane >= ii + 1) {
                float s = 0.f;
                for (int c = ii + 1; c < 10; c++) {
                    float av = (lane >= c) ? A[lane][c] : A[c][lane];
                    s += av * A[c][ii];
                }
                wsh[lane] = taui * s;
            }
            __syncwarp(M);
            float dot = 0.f;
            for (int r = ii + 1; r < 10; r++) dot += wsh[r] * A[r][ii];
            float alw = -0.5f * taui * dot;
            __syncwarp(M);                       // reads of wsh complete
            if (lane >= ii + 1) wsh[lane] += alw * A[lane][ii];
            __syncwarp(M);
            // rank-2 update: lane r owns row r (writes lower triangle only)
            if (lane >= ii + 1) {
                for (int c = ii + 1; c <= lane; c++)
                    A[lane][c] -= A[lane][ii] * wsh[c] + wsh[lane] * A[c][ii];
            }
            __syncwarp(M);
            if (lane == ii + 1) A[ii + 1][ii] = eel[ii];
        }
        taul[ii] = taui;
    }
    __syncwarp(M);
    for (int k = 0; k < 10; k++) ddl[k] = A[k][k];

    // =======================================================================
    // Q = H(1)..H(n-1): lane j owns column j, fully independent (reads A only)
    // =======================================================================
    float qc[10];
#pragma unroll
    for (int r = 0; r < 10; r++) qc[r] = (r == lane) ? 1.f : 0.f;
#pragma unroll
    for (int ii = 8; ii >= 0; ii--) {
        float taui = taul[ii];
        if (taui != 0.f) {
            float s = 0.f;
#pragma unroll
            for (int r = 0; r < 10; r++) {
                if (r == ii + 1)      s += qc[r];
                else if (r >= ii + 2) s += A[r][ii] * qc[r];
            }
            s *= taui;
#pragma unroll
            for (int r = 0; r < 10; r++) {
                if (r == ii + 1)      qc[r] -= s;
                else if (r >= ii + 2) qc[r] -= A[r][ii] * s;
            }
        }
    }
    // transpose: lane j writes column j; then lane i loads row i into registers
#pragma unroll
    for (int r = 0; r < 10; r++) Zsh[r][lane] = qc[r];
    __syncwarp(M);
    float z[10];
#pragma unroll
    for (int c = 0; c < 10; c++) z[c] = Zsh[lane][c];

    // =======================================================================
    // ssteqr ('V'): scalar driver replicated per-lane (private ddl/eel/wcl/wsl),
    // Z rotations applied to this lane's row registers only. No syncs needed.
    // =======================================================================
#define D1(k)   ddl[(k) - 1]
#define E1(k)   eel[(k) - 1]
#define WC1(k)  wcl[(k) - 1]
#define WS1(k)  wsl[(k) - 1]
    const float EPS    = 5.9604645e-08f;
    const float EPS2   = EPS * EPS;
    const float SAFMIN = 1.1754944e-38f;
    int n = 10, nmaxit = n * 30, jtot = 0;
    int l1 = 1, l = 0, lsv, lend, lendsv, m;
    float p, g, r, c, s, f, b, rt1, rt2;

L10:
    if (l1 > n) goto L160;
    if (l1 > 1) E1(l1 - 1) = 0.f;
    if (l1 <= n - 1) {
        for (m = l1; m <= n - 1; m++) {
            float tst = fabsf(E1(m));
            if (tst == 0.f) goto L30;
            if (tst <= (sqrtf(fabsf(D1(m))) * sqrtf(fabsf(D1(m + 1)))) * EPS) {
                E1(m) = 0.f; goto L30;
            }
        }
    }
    m = n;
L30:
    l = l1; lsv = l; lend = m; lendsv = lend; l1 = m + 1;
    if (lend == l) goto L10;
    if (fabsf(D1(lend)) < fabsf(D1(l))) { lend = lsv; l = lendsv; }
    if (lend > l) goto L40; else goto L90;

    // ============ QL iteration ============
L40:
    if (l != lend) {
        int found = 0;
        for (m = l; m <= lend - 1; m++) {
            float tst = E1(m) * E1(m);
            if (tst <= EPS2 * fabsf(D1(m)) * fabsf(D1(m + 1)) + SAFMIN) { found = 1; break; }
        }
        if (!found) m = lend;
    } else m = lend;
    if (m < lend) E1(m) = 0.f;
    p = D1(l);
    if (m == l) goto L80;
    if (m == l + 1) {
        slaev2_(D1(l), E1(l), D1(l + 1), &rt1, &rt2, &c, &s);
        {   // rotate columns (l, l+1): jj = l-1
#pragma unroll
            for (int jj = 0; jj < 9; jj++) if (jj == l - 1) {
                float tmp = z[jj + 1];
                z[jj + 1] = c * tmp - s * z[jj];
                z[jj]     = s * tmp + c * z[jj];
            }
        }
        D1(l) = rt1; D1(l + 1) = rt2; E1(l) = 0.f;
        l += 2;
        if (l <= lend) goto L40;
        goto L140;
    }
    if (jtot == nmaxit) goto L140;
    jtot++;
    g = (D1(l + 1) - p) / (2.f * E1(l));
    r = slapy2_(g, 1.f);
    g = D1(m) - p + E1(l) / (g + signf_(r, g));
    s = 1.f; c = 1.f; p = 0.f;
    for (int i = m - 1; i >= l; i--) {
        f = s * E1(i); b = c * E1(i);
        slartg_(g, f, &c, &s, &r);
        if (i != m - 1) E1(i + 1) = r;
        g = D1(i + 1) - p;
        r = (D1(i) - g) * s + 2.f * c * b;
        p = s * r;
        D1(i + 1) = g + p;
        g = c * r - b;
        WC1(i) = c; WS1(i) = -s;
    }
    {   // slasr 'R','V','B': j1 = m-1 .. l, rotate cols (j1, j1+1); jj = j1-1
#pragma unroll
        for (int jj = 8; jj >= 0; jj--) {
            if (jj >= l - 1 && jj <= m - 2) {
                float ct = wcl[jj], st = wsl[jj];
                float tmp = z[jj + 1];
                z[jj + 1] = ct * tmp - st * z[jj];
                z[jj]     = st * tmp + ct * z[jj];
            }
        }
    }
    D1(l) -= p; E1(l) = g;
    goto L40;
L80:
    D1(l) = p;
    l++;
    if (l <= lend) goto L40;
    goto L140;

    // ============ QR iteration ============
L90:
    if (l != lend) {
        int found = 0;
        for (m = l; m >= lend + 1; m--) {
            float tst = E1(m - 1) * E1(m - 1);
            if (tst <= EPS2 * fabsf(D1(m)) * fabsf(D1(m - 1)) + SAFMIN) { found = 1; break; }
        }
        if (!found) m = lend;
    } else m = lend;
    if (m > lend) E1(m - 1) = 0.f;
    p = D1(l);
    if (m == l) goto L130;
    if (m == l - 1) {
        slaev2_(D1(l - 1), E1(l - 1), D1(l), &rt1, &rt2, &c, &s);
        {   // rotate columns (l-1, l): jj = l-2
#pragma unroll
            for (int jj = 0; jj < 9; jj++) if (jj == l - 2) {
                float tmp = z[jj + 1];
                z[jj + 1] = c * tmp - s * z[jj];
                z[jj]     = s * tmp + c * z[jj];
            }
        }
        D1(l - 1) = rt1; D1(l) = rt2; E1(l - 1) = 0.f;
        l -= 2;
        if (l >= lend) goto L90;
        goto L140;
    }
    if (jtot == nmaxit) goto L140;
    jtot++;
    g = (D1(l - 1) - p) / (2.f * E1(l - 1));
    r = slapy2_(g, 1.f);
    g = D1(m) - p + E1(l - 1) / (g + signf_(r, g));
    s = 1.f; c = 1.f; p = 0.f;
    for (int i = m; i <= l - 1; i++) {
        f = s * E1(i); b = c * E1(i);
        slartg_(g, f, &c, &s, &r);
        if (i != m) E1(i - 1) = r;
        g = D1(i) - p;
        r = (D1(i + 1) - g) * s + 2.f * c * b;
        p = s * r;
        D1(i) = g + p;
        g = c * r - b;
        WC1(i) = c; WS1(i) = s;
    }
    {   // slasr 'R','V','F': j1 = m .. l-1, rotate cols (j1, j1+1); jj = j1-1
#pragma unroll
        for (int jj = 0; jj <= 8; jj++) {
            if (jj >= m - 1 && jj <= l - 2) {
                float ct = wcl[jj], st = wsl[jj];
                float tmp = z[jj + 1];
                z[jj + 1] = ct * tmp - st * z[jj];
                z[jj]     = st * tmp + ct * z[jj];
            }
        }
    }
    D1(l) -= p; E1(l - 1) = g;
    goto L90;
L130:
    D1(l) = p;
    l--;
    if (l >= lend) goto L90;
    goto L140;

L140:
    if (jtot < nmaxit) goto L10;
    goto L160;

L160:
    // LAPACK ascending selection sort with column swaps (per-lane on registers)
    for (int ii2 = 2; ii2 <= n; ii2++) {
        int i = ii2 - 1, k = i;
        float pp = D1(i);
        for (int j = ii2; j <= n; j++)
            if (D1(j) < pp) { k = j; pp = D1(j); }
        if (k != i) {
            D1(k) = D1(i); D1(i) = pp;
            float zi = 0.f, zk = 0.f;
#pragma unroll
            for (int cidx = 0; cidx < 10; cidx++) {
                if (cidx == i - 1) zi = z[cidx];
                if (cidx == k - 1) zk = z[cidx];
            }
#pragma unroll
            for (int cidx = 0; cidx < 10; cidx++) {
                if (cidx == i - 1) z[cidx] = zk;
                if (cidx == k - 1) z[cidx] = zi;
            }
        }
    }

    // ---- MLP per-lane: lane i computes output row i --------------------------
    {
        float y2 = sb2[0];
#pragma unroll
        for (int h = 0; h < 16; h++) {
            float a1 = sb1[h];
#pragma unroll
            for (int j = 0; j < 10; j++) a1 = fmaf(z[j], sW1[h * 10 + j], a1);
            a1 = fmaxf(a1, 0.f);
            y2 = fmaf(a1, sW2[h], y2);
        }
        out[lane] = 0.5f * (1.f / (1.f + expf(-y2)) + 1.f);
    }
#undef D1
#undef E1
#undef WC1
#undef WS1
}

extern "C" void kernel_launch(void* const* d_in, const int* in_sizes, int n_in,
                              void* d_out, int out_size)
{
    const float* x  = (const float*)d_in[0];
    const float* W1 = (const float*)d_in[1];
    const float* b1 = (const float*)d_in[2];
    const float* W2 = (const float*)d_in[3];
    const float* b2 = (const float*)d_in[4];
    int nrows = in_sizes[0] / 10;
    int units = nrows / 2;
    gram_kernel<<<NBLK, TPB>>>(x, units, nrows);
    finish_kernel<<<1, 512>>>(W1, b1, W2, b2, (float*)d_out);
}

// round 4
// speedup vs baseline: 1.2678x; 1.0626x over previous
#include <cuda_runtime.h>
#include <math.h>

#define NBLK 2368
#define TPB  128

// Per-block partial sums of the 55 unique Gram entries.
__device__ float g_part[NBLK][55];

__device__ __forceinline__ constexpr int tri_idx(int i, int j) {
    return i * 10 - (i * (i + 1)) / 2 + j;   // i <= j
}

// ---------------------------------------------------------------------------
// Kernel 1: deterministic Gram partial reduction.
// 2-row units (80B = 5 aligned float4 loads); products accumulated with packed
// fma.rn.f32x2 (FFMA2): lane.lo accumulates even rows, lane.hi odd rows.
// ---------------------------------------------------------------------------
__global__ __launch_bounds__(TPB, 3) void gram_kernel(const float* __restrict__ x,
                                                      int units, int nrows)
{
    const float4* __restrict__ xv = (const float4*)x;
    unsigned long long acc2[55];
#pragma unroll
    for (int k = 0; k < 55; k++) acc2[k] = 0ull;   // {+0.f, +0.f}

    int tid = blockIdx.x * TPB + threadIdx.x;
    const int stride = NBLK * TPB;
    for (int p = tid; p < units; p += stride) {
        float v[20];
        int base = 5 * p;
        float4 q;
        q = xv[base + 0]; v[0]  = q.x; v[1]  = q.y; v[2]  = q.z; v[3]  = q.w;
        q = xv[base + 1]; v[4]  = q.x; v[5]  = q.y; v[6]  = q.z; v[7]  = q.w;
        q = xv[base + 2]; v[8]  = q.x; v[9]  = q.y; v[10] = q.z; v[11] = q.w;
        q = xv[base + 3]; v[12] = q.x; v[13] = q.y; v[14] = q.z; v[15] = q.w;
        q = xv[base + 4]; v[16] = q.x; v[17] = q.y; v[18] = q.z; v[19] = q.w;
        unsigned long long vp[10];
#pragma unroll
        for (int i = 0; i < 10; i++)
            asm("mov.b64 %0, {%1, %2};" : "=l"(vp[i]) : "f"(v[i]), "f"(v[10 + i]));
#pragma unroll
        for (int i = 0; i < 10; i++)
#pragma unroll
            for (int j = i; j < 10; j++)
                asm("fma.rn.f32x2 %0, %1, %2, %0;"
                    : "+l"(acc2[tri_idx(i, j)]) : "l"(vp[i]), "l"(vp[j]));
    }

    float acc[55];
#pragma unroll
    for (int k = 0; k < 55; k++) {
        float lo, hi;
        asm("mov.b64 {%0, %1}, %2;" : "=f"(lo), "=f"(hi) : "l"(acc2[k]));
        acc[k] = lo + hi;
    }

    // Odd trailing row (not hit for N=4M, kept for shape robustness).
    if (tid == 0 && (nrows & 1)) {
        const float* last = x + (size_t)(nrows - 1) * 10;
        float v[10];
#pragma unroll
        for (int i = 0; i < 10; i++) v[i] = last[i];
#pragma unroll
        for (int i = 0; i < 10; i++)
#pragma unroll
            for (int j = i; j < 10; j++)
                acc[tri_idx(i, j)] = fmaf(v[i], v[j], acc[tri_idx(i, j)]);
    }

    // Deterministic warp shuffle tree reduce per entry.
#pragma unroll
    for (int k = 0; k < 55; k++) {
#pragma unroll
        for (int off = 16; off > 0; off >>= 1)
            acc[k] += __shfl_down_sync(0xffffffffu, acc[k], off);
    }
    __shared__ float red[TPB / 32][55];
    int lane = threadIdx.x & 31, wid = threadIdx.x >> 5;
    if (lane == 0) {
#pragma unroll
        for (int k = 0; k < 55; k++) red[wid][k] = acc[k];
    }
    __syncthreads();
    if (threadIdx.x < 55) {
        float s = 0.f;
#pragma unroll
        for (int w = 0; w < TPB / 32; w++) s += red[w][threadIdx.x];
        g_part[blockIdx.x][threadIdx.x] = s;
    }
}

// ---------------------------------------------------------------------------
// LAPACK-faithful fp32 helpers
// ---------------------------------------------------------------------------
__device__ __forceinline__ float signf_(float a, float b) {
    return b >= 0.f ? fabsf(a) : -fabsf(a);
}
__device__ __forceinline__ float slapy2_(float xx, float yy) {
    float xa = fabsf(xx), ya = fabsf(yy);
    float w = fmaxf(xa, ya), zz = fminf(xa, ya);
    if (zz == 0.f) return w;
    float t = zz / w;
    return w * sqrtf(1.f + t * t);
}
__device__ __forceinline__ void slartg_(float f, float g, float* cs, float* sn, float* r) {
    if (g == 0.f)      { *cs = 1.f; *sn = 0.f; *r = f; }
    else if (f == 0.f) { *cs = 0.f; *sn = (g >= 0.f ? 1.f : -1.f); *r = fabsf(g); }
    else {
        float d  = sqrtf(f * f + g * g);
        *cs = fabsf(f) / d;
        float rr = (f >= 0.f ? d : -d);
        *r = rr;
        *sn = g / rr;
    }
}
__device__ __forceinline__ void slaev2_(float a, float b, float cc,
                        float* rt1, float* rt2, float* cs1o, float* sn1o) {
    float sm = a + cc, df = a - cc;
    float adf = fabsf(df), tb = b + b, ab = fabsf(tb);
    float acmx, acmn;
    if (fabsf(a) > fabsf(cc)) { acmx = a;  acmn = cc; }
    else                      { acmx = cc; acmn = a;  }
    float rt;
    if (adf > ab)      { float t = ab / adf;  rt = adf * sqrtf(1.f + t * t); }
    else if (adf < ab) { float t = adf / ab;  rt = ab  * sqrtf(1.f + t * t); }
    else               rt = ab * sqrtf(2.f);
    int sgn1;
    if (sm < 0.f)      { *rt1 = 0.5f * (sm - rt); sgn1 = -1;
                         *rt2 = (acmx / *rt1) * acmn - (b / *rt1) * b; }
    else if (sm > 0.f) { *rt1 = 0.5f * (sm + rt); sgn1 = 1;
                         *rt2 = (acmx / *rt1) * acmn - (b / *rt1) * b; }
    else               { *rt1 = 0.5f * rt; *rt2 = -0.5f * rt; sgn1 = 1; }
    float cs; int sgn2;
    if (df >= 0.f) { cs = df + rt; sgn2 = 1; }
    else           { cs = df - rt; sgn2 = -1; }
    float acs = fabsf(cs), c1, s1;
    if (acs > ab) { float ct = -tb / cs; s1 = 1.f / sqrtf(1.f + ct * ct); c1 = ct * s1; }
    else {
        if (ab == 0.f) { c1 = 1.f; s1 = 0.f; }
        else { float tn = -cs / tb; c1 = 1.f / sqrtf(1.f + tn * tn); s1 = tn * c1; }
    }
    if (sgn1 == sgn2) { float t = c1; c1 = -s1; s1 = t; }
    *cs1o = c1; *sn1o = s1;
}

// Predicated register-array access (1-based index); keeps arrays in registers.
__device__ __forceinline__ float rget10(const float (&a)[10], int k1) {
    float v = a[0];
#pragma unroll
    for (int k = 2; k <= 10; k++) if (k1 == k) v = a[k - 1];
    return v;
}
__device__ __forceinline__ void rset10(float (&a)[10], int k1, float v) {
#pragma unroll
    for (int k = 1; k <= 10; k++) if (k1 == k) a[k - 1] = v;
}

// ---------------------------------------------------------------------------
// Kernel 2: parallel reduce -> fp32 gram -> register-resident LAPACK-clone
// eigensolver (static-unrolled ssteqr; no local-memory arrays) -> MLP.
// 512 threads x <=128 regs fits the regfile (R3 failed at 896 threads).
// ---------------------------------------------------------------------------
__global__ __launch_bounds__(512, 1)
void finish_kernel(const float* __restrict__ W1, const float* __restrict__ b1,
                   const float* __restrict__ W2, const float* __restrict__ b2,
                   float* __restrict__ out)
{
    __shared__ double part[55][8];
    __shared__ float A[10][10];
    __shared__ float Zsh[10][10];
    __shared__ float wsh[10];
    __shared__ float sW1[160], sb1[16], sW2[16], sb2[1];

    int t = threadIdx.x;

    // ---- preload MLP weights (threads 440..) ----
    if (t >= 440 && t < 472) {
        int k = t - 440;
#pragma unroll
        for (int r = 0; r < 5; r++) sW1[k * 5 + r] = W1[k * 5 + r];
        if (k < 16) { sb1[k] = b1[k]; sW2[k] = W2[k]; }
        if (k == 0) sb2[0] = b2[0];
    }

    // ---- parallel deterministic double reduction: 55 entries x 8 partitions ----
    if (t < 440) {
        int e = t >> 3, q = t & 7;
        int b0 = q * (NBLK / 8);               // 296 blocks per partition
        double a0 = 0.0, a1 = 0.0, a2 = 0.0, a3 = 0.0;
        for (int b = 0; b < NBLK / 8; b += 4) {
            a0 += (double)g_part[b0 + b + 0][e];
            a1 += (double)g_part[b0 + b + 1][e];
            a2 += (double)g_part[b0 + b + 2][e];
            a3 += (double)g_part[b0 + b + 3][e];
        }
        part[e][q] = (a0 + a1) + (a2 + a3);
    }
    __syncthreads();
    if (t < 55) {
        double s = 0.0;
#pragma unroll
        for (int q = 0; q < 8; q++) s += part[t][q];   // fixed order
        int i = 0, rem = t;
        while (rem >= 10 - i) { rem -= 10 - i; i++; }
        int j = i + rem;
        float fv = (float)s;
        A[i][j] = fv; A[j][i] = fv;
    }
    __syncthreads();
    if (t >= 32) return;
    const unsigned M = 0x3ffu;
    int lane = t;
    if (lane >= 10) return;

    // =======================================================================
    // ssytd2 (UPLO='L'), lane-parallel; ereg/taul static-indexed registers.
    // =======================================================================
    float dreg[10], ereg[10], wcr[10], wsr[10], taul[9];
#pragma unroll
    for (int ii = 0; ii < 9; ii++) {
        __syncwarp(M);
        float alpha = A[ii + 1][ii];
        float xn2 = 0.f;
#pragma unroll
        for (int r2 = ii + 2; r2 < 10; r2++) xn2 += A[r2][ii] * A[r2][ii];
        float xnorm = sqrtf(xn2);
        float taui;
        if (xnorm == 0.f) {
            taui = 0.f;
            ereg[ii] = alpha;
        } else {
            float beta = -signf_(slapy2_(alpha, xnorm), alpha);
            taui = (beta - alpha) / beta;
            float sc = 1.f / (alpha - beta);
            ereg[ii] = beta;
            __syncwarp(M);                       // all lanes done reading col ii
            if (lane >= ii + 2) A[lane][ii] *= sc;
            if (lane == ii + 1) A[ii + 1][ii] = 1.f;
            __syncwarp(M);
            if (lane >= ii + 1) {
                float s = 0.f;
#pragma unroll
                for (int c2 = ii + 1; c2 < 10; c2++) {
                    float av = (lane >= c2) ? A[lane][c2] : A[c2][lane];
                    s += av * A[c2][ii];
                }
                wsh[lane] = taui * s;
            }
            __syncwarp(M);
            float dot = 0.f;
#pragma unroll
            for (int r2 = ii + 1; r2 < 10; r2++) dot += wsh[r2] * A[r2][ii];
            float alw = -0.5f * taui * dot;
            __syncwarp(M);
            if (lane >= ii + 1) wsh[lane] += alw * A[lane][ii];
            __syncwarp(M);
            if (lane >= ii + 1) {
                for (int c2 = ii + 1; c2 <= lane; c2++)
                    A[lane][c2] -= A[lane][ii] * wsh[c2] + wsh[lane] * A[c2][ii];
            }
            __syncwarp(M);
            if (lane == ii + 1) A[ii + 1][ii] = ereg[ii];
        }
        taul[ii] = taui;
    }
    __syncwarp(M);
#pragma unroll
    for (int k = 0; k < 10; k++) dreg[k] = A[k][k];

    // =======================================================================
    // Q = H(1)..H(n-1): lane j owns column j.
    // =======================================================================
    float qc[10];
#pragma unroll
    for (int r2 = 0; r2 < 10; r2++) qc[r2] = (r2 == lane) ? 1.f : 0.f;
#pragma unroll
    for (int ii = 8; ii >= 0; ii--) {
        float taui = taul[ii];
        if (taui != 0.f) {
            float s = 0.f;
#pragma unroll
            for (int r2 = 0; r2 < 10; r2++) {
                if (r2 == ii + 1)      s += qc[r2];
                else if (r2 >= ii + 2) s += A[r2][ii] * qc[r2];
            }
            s *= taui;
#pragma unroll
            for (int r2 = 0; r2 < 10; r2++) {
                if (r2 == ii + 1)      qc[r2] -= s;
                else if (r2 >= ii + 2) qc[r2] -= A[r2][ii] * s;
            }
        }
    }
#pragma unroll
    for (int r2 = 0; r2 < 10; r2++) Zsh[r2][lane] = qc[r2];
    __syncwarp(M);
    float z[10];
#pragma unroll
    for (int c2 = 0; c2 < 10; c2++) z[c2] = Zsh[lane][c2];

    // =======================================================================
    // ssteqr ('V'), fully register-resident; scalar driver replicated per-lane.
    // =======================================================================
    {
    const float EPS    = 5.9604645e-08f;
    const float EPS2   = EPS * EPS;
    const float SAFMIN = 1.1754944e-38f;
    int n = 10, nmaxit = n * 30, jtot = 0;
    int l1 = 1, l = 0, lsv, lend, lendsv, m;
    float p, g, r, c, s, f, b, rt1, rt2;

L10:
    if (l1 > n) goto L160;
    if (l1 > 1) rset10(ereg, l1 - 1, 0.f);
    if (l1 <= n - 1) {
        int msel = n; bool fnd = false;
#pragma unroll
        for (int mm = 1; mm <= 9; mm++) {
            if (!fnd && mm >= l1) {
                float tst = fabsf(ereg[mm - 1]);
                if (tst == 0.f) { msel = mm; fnd = true; }
                else if (tst <= (sqrtf(fabsf(dreg[mm - 1])) * sqrtf(fabsf(dreg[mm]))) * EPS) {
                    ereg[mm - 1] = 0.f; msel = mm; fnd = true;
                }
            }
        }
        m = msel;
    } else m = n;
// L30:
    l = l1; lsv = l; lend = m; lendsv = lend; l1 = m + 1;
    if (lend == l) goto L10;
    if (fabsf(rget10(dreg, lend)) < fabsf(rget10(dreg, l))) { lend = lsv; l = lendsv; }
    if (lend > l) goto L40; else goto L90;

    // ============ QL iteration ============
L40:
    if (l != lend) {
        int msel = lend; bool fnd = false;
#pragma unroll
        for (int mm = 1; mm <= 9; mm++) {
            if (!fnd && mm >= l && mm <= lend - 1) {
                float tst = ereg[mm - 1] * ereg[mm - 1];
                if (tst <= EPS2 * fabsf(dreg[mm - 1]) * fabsf(dreg[mm]) + SAFMIN) {
                    msel = mm; fnd = true;
                }
            }
        }
        m = msel;
    } else m = lend;
    if (m < lend) rset10(ereg, m, 0.f);
    p = rget10(dreg, l);
    if (m == l) goto L80;
    if (m == l + 1) {
        slaev2_(rget10(dreg, l), rget10(ereg, l), rget10(dreg, l + 1), &rt1, &rt2, &c, &s);
#pragma unroll
        for (int jj = 0; jj < 9; jj++) if (jj == l - 1) {
            float tmp = z[jj + 1];
            z[jj + 1] = c * tmp - s * z[jj];
            z[jj]     = s * tmp + c * z[jj];
        }
        rset10(dreg, l, rt1); rset10(dreg, l + 1, rt2); rset10(ereg, l, 0.f);
        l += 2;
        if (l <= lend) goto L40;
        goto L140;
    }
    if (jtot == nmaxit) goto L140;
    jtot++;
    g = (rget10(dreg, l + 1) - p) / (2.f * rget10(ereg, l));
    r = slapy2_(g, 1.f);
    g = rget10(dreg, m) - p + rget10(ereg, l) / (g + signf_(r, g));
    s = 1.f; c = 1.f; p = 0.f;
#pragma unroll
    for (int i = 9; i >= 1; i--) {
        if (i <= m - 1 && i >= l) {
            f = s * ereg[i - 1]; b = c * ereg[i - 1];
            slartg_(g, f, &c, &s, &r);
            if (i != m - 1) ereg[i] = r;
            g = dreg[i] - p;
            r = (dreg[i - 1] - g) * s + 2.f * c * b;
            p = s * r;
            dreg[i] = g + p;
            g = c * r - b;
            wcr[i - 1] = c; wsr[i - 1] = -s;
        }
    }
#pragma unroll
    for (int jj = 8; jj >= 0; jj--) {
        if (jj >= l - 1 && jj <= m - 2) {
            float ct = wcr[jj], st = wsr[jj];
            float tmp = z[jj + 1];
            z[jj + 1] = ct * tmp - st * z[jj];
            z[jj]     = st * tmp + ct * z[jj];
        }
    }
    rset10(dreg, l, rget10(dreg, l) - p);
    rset10(ereg, l, g);
    goto L40;
L80:
    rset10(dreg, l, p);
    l++;
    if (l <= lend) goto L40;
    goto L140;

    // ============ QR iteration ============
L90:
    if (l != lend) {
        int msel = lend; bool fnd = false;
#pragma unroll
        for (int mm = 10; mm >= 2; mm--) {
            if (!fnd && mm <= l && mm >= lend + 1) {
                float tst = ereg[mm - 2] * ereg[mm - 2];
                if (tst <= EPS2 * fabsf(dreg[mm - 1]) * fabsf(dreg[mm - 2]) + SAFMIN) {
                    msel = mm; fnd = true;
                }
            }
        }
        m = msel;
    } else m = lend;
    if (m > lend) rset10(ereg, m - 1, 0.f);
    p = rget10(dreg, l);
    if (m == l) goto L130;
    if (m == l - 1) {
        slaev2_(rget10(dreg, l - 1), rget10(ereg, l - 1), rget10(dreg, l), &rt1, &rt2, &c, &s);
#pragma unroll
        for (int jj = 0; jj < 9; jj++) if (jj == l - 2) {
            float tmp = z[jj + 1];
            z[jj + 1] = c * tmp - s * z[jj];
            z[jj]     = s * tmp + c * z[jj];
        }
        rset10(dreg, l - 1, rt1); rset10(dreg, l, rt2); rset10(ereg, l - 1, 0.f);
        l -= 2;
        if (l >= lend) goto L90;
        goto L140;
    }
    if (jtot == nmaxit) goto L140;
    jtot++;
    g = (rget10(dreg, l - 1) - p) / (2.f * rget10(ereg, l - 1));
    r = slapy2_(g, 1.f);
    g = rget10(dreg, m) - p + rget10(ereg, l - 1) / (g + signf_(r, g));
    s = 1.f; c = 1.f; p = 0.f;
#pragma unroll
    for (int i = 1; i <= 9; i++) {
        if (i >= m && i <= l - 1) {
            f = s * ereg[i - 1]; b = c * ereg[i - 1];
            slartg_(g, f, &c, &s, &r);
            if (i >= 2) { if (i != m) ereg[i - 2] = r; }
            g = dreg[i - 1] - p;
            r = (dreg[i] - g) * s + 2.f * c * b;
            p = s * r;
            dreg[i - 1] = g + p;
            g = c * r - b;
            wcr[i - 1] = c; wsr[i - 1] = s;
        }
    }
#pragma unroll
    for (int jj = 0; jj <= 8; jj++) {
        if (jj >= m - 1 && jj <= l - 2) {
            float ct = wcr[jj], st = wsr[jj];
            float tmp = z[jj + 1];
            z[jj + 1] = ct * tmp - st * z[jj];
            z[jj]     = st * tmp + ct * z[jj];
        }
    }
    rset10(dreg, l, rget10(dreg, l) - p);
    rset10(ereg, l - 1, g);
    goto L90;
L130:
    rset10(dreg, l, p);
    l--;
    if (l >= lend) goto L90;
    goto L140;

L140:
    if (jtot < nmaxit) goto L10;
    goto L160;

L160:
    // LAPACK ascending selection sort with column swaps.
    for (int ii2 = 2; ii2 <= n; ii2++) {
        int i = ii2 - 1, k = i;
        float pp = rget10(dreg, i);
#pragma unroll
        for (int j = 2; j <= 10; j++) {
            if (j >= ii2) {
                float dj = dreg[j - 1];
                if (dj < pp) { k = j; pp = dj; }
            }
        }
        if (k != i) {
            rset10(dreg, k, rget10(dreg, i));
            rset10(dreg, i, pp);
            float zi = 0.f, zk = 0.f;
#pragma unroll
            for (int cidx = 0; cidx < 10; cidx++) {
                if (cidx == i - 1) zi = z[cidx];
                if (cidx == k - 1) zk = z[cidx];
            }
#pragma unroll
            for (int cidx = 0; cidx < 10; cidx++) {
                if (cidx == i - 1) z[cidx] = zk;
                if (cidx == k - 1) z[cidx] = zi;
            }
        }
    }
    }

    // ---- MLP per-lane: lane i computes output row i ------------------------
    {
        float y2 = sb2[0];
#pragma unroll
        for (int h = 0; h < 16; h++) {
            float a1 = sb1[h];
#pragma unroll
            for (int j = 0; j < 10; j++) a1 = fmaf(z[j], sW1[h * 10 + j], a1);
            a1 = fmaxf(a1, 0.f);
            y2 = fmaf(a1, sW2[h], y2);
        }
        out[lane] = 0.5f * (1.f / (1.f + expf(-y2)) + 1.f);
    }
}

extern "C" void kernel_launch(void* const* d_in, const int* in_sizes, int n_in,
                              void* d_out, int out_size)
{
    const float* x  = (const float*)d_in[0];
    const float* W1 = (const float*)d_in[1];
    const float* b1 = (const float*)d_in[2];
    const float* W2 = (const float*)d_in[3];
    const float* b2 = (const float*)d_in[4];
    int nrows = in_sizes[0] / 10;
    int units = nrows / 2;
    gram_kernel<<<NBLK, TPB>>>(x, units, nrows);
    finish_kernel<<<1, 512>>>(W1, b1, W2, b2, (float*)d_out);
}

// round 5
// speedup vs baseline: 1.3335x; 1.0518x over previous
#include <cuda_runtime.h>
#include <math.h>

#define NBLK 2368
#define TPB  128

// Per-block partial sums of the 55 unique Gram entries.
__device__ float g_part[NBLK][55];

__device__ __forceinline__ constexpr int tri_idx(int i, int j) {
    return i * 10 - (i * (i + 1)) / 2 + j;   // i <= j
}

// ---------------------------------------------------------------------------
// Kernel 1: deterministic Gram partial reduction (FFMA2 packed accumulate).
// ---------------------------------------------------------------------------
__global__ __launch_bounds__(TPB, 3) void gram_kernel(const float* __restrict__ x,
                                                      int units, int nrows)
{
    const float4* __restrict__ xv = (const float4*)x;
    unsigned long long acc2[55];
#pragma unroll
    for (int k = 0; k < 55; k++) acc2[k] = 0ull;   // {+0.f, +0.f}

    int tid = blockIdx.x * TPB + threadIdx.x;
    const int stride = NBLK * TPB;
    for (int p = tid; p < units; p += stride) {
        float v[20];
        int base = 5 * p;
        float4 q;
        q = xv[base + 0]; v[0]  = q.x; v[1]  = q.y; v[2]  = q.z; v[3]  = q.w;
        q = xv[base + 1]; v[4]  = q.x; v[5]  = q.y; v[6]  = q.z; v[7]  = q.w;
        q = xv[base + 2]; v[8]  = q.x; v[9]  = q.y; v[10] = q.z; v[11] = q.w;
        q = xv[base + 3]; v[12] = q.x; v[13] = q.y; v[14] = q.z; v[15] = q.w;
        q = xv[base + 4]; v[16] = q.x; v[17] = q.y; v[18] = q.z; v[19] = q.w;
        unsigned long long vp[10];
#pragma unroll
        for (int i = 0; i < 10; i++)
            asm("mov.b64 %0, {%1, %2};" : "=l"(vp[i]) : "f"(v[i]), "f"(v[10 + i]));
#pragma unroll
        for (int i = 0; i < 10; i++)
#pragma unroll
            for (int j = i; j < 10; j++)
                asm("fma.rn.f32x2 %0, %1, %2, %0;"
                    : "+l"(acc2[tri_idx(i, j)]) : "l"(vp[i]), "l"(vp[j]));
    }

    float acc[55];
#pragma unroll
    for (int k = 0; k < 55; k++) {
        float lo, hi;
        asm("mov.b64 {%0, %1}, %2;" : "=f"(lo), "=f"(hi) : "l"(acc2[k]));
        acc[k] = lo + hi;
    }

    if (tid == 0 && (nrows & 1)) {
        const float* last = x + (size_t)(nrows - 1) * 10;
        float v[10];
#pragma unroll
        for (int i = 0; i < 10; i++) v[i] = last[i];
#pragma unroll
        for (int i = 0; i < 10; i++)
#pragma unroll
            for (int j = i; j < 10; j++)
                acc[tri_idx(i, j)] = fmaf(v[i], v[j], acc[tri_idx(i, j)]);
    }

#pragma unroll
    for (int k = 0; k < 55; k++) {
#pragma unroll
        for (int off = 16; off > 0; off >>= 1)
            acc[k] += __shfl_down_sync(0xffffffffu, acc[k], off);
    }
    __shared__ float red[TPB / 32][55];
    int lane = threadIdx.x & 31, wid = threadIdx.x >> 5;
    if (lane == 0) {
#pragma unroll
        for (int k = 0; k < 55; k++) red[wid][k] = acc[k];
    }
    __syncthreads();
    if (threadIdx.x < 55) {
        float s = 0.f;
#pragma unroll
        for (int w = 0; w < TPB / 32; w++) s += red[w][threadIdx.x];
        g_part[blockIdx.x][threadIdx.x] = s;
    }
}

// ---------------------------------------------------------------------------
// Fast approx primitives (MUFU; <=2^-23 rel err). Values in this problem are
// well away from denormal/overflow, so ftz variants are safe.
// ---------------------------------------------------------------------------
__device__ __forceinline__ float frcp_(float x) {
    float r; asm("rcp.approx.ftz.f32 %0, %1;" : "=f"(r) : "f"(x)); return r;
}
__device__ __forceinline__ float frsqrt_(float x) {
    float r; asm("rsqrt.approx.ftz.f32 %0, %1;" : "=f"(r) : "f"(x)); return r;
}
__device__ __forceinline__ float fsqrt_(float x) {          // x >= 0
    return (x > 0.f) ? x * frsqrt_(x) : 0.f;
}

__device__ __forceinline__ float signf_(float a, float b) {
    return b >= 0.f ? fabsf(a) : -fabsf(a);
}
// hypot(g, 1)
__device__ __forceinline__ float slapy2_1_(float g) {
    float t = fmaf(g, g, 1.f);
    return t * frsqrt_(t);
}
// Branchless Givens (LAPACK sign convention), rsqrt-based.
__device__ __forceinline__ void slartg_(float f, float g, float* cs, float* sn, float* r) {
    float f2   = fmaf(f, f, g * g);
    float rinv = frsqrt_(f2);
    float d    = f2 * rinv;
    float sgn  = (f >= 0.f) ? 1.f : -1.f;
    float cs0  = fabsf(f) * rinv;
    float sn0  = g * rinv * sgn;
    float r0   = sgn * d;
    bool gz = (g == 0.f), fz = (f == 0.f);
    *cs = gz ? 1.f : (fz ? 0.f                      : cs0);
    *sn = gz ? 0.f : (fz ? ((g >= 0.f) ? 1.f : -1.f): sn0);
    *r  = gz ? f   : (fz ? fabsf(g)                 : r0);
}
__device__ __forceinline__ void slaev2_(float a, float b, float cc,
                        float* rt1, float* rt2, float* cs1o, float* sn1o) {
    float sm = a + cc, df = a - cc;
    float adf = fabsf(df), tb = b + b, ab = fabsf(tb);
    float acmx, acmn;
    if (fabsf(a) > fabsf(cc)) { acmx = a;  acmn = cc; }
    else                      { acmx = cc; acmn = a;  }
    float rt;
    if (adf > ab)      { float t = ab * frcp_(adf); float h = fmaf(t, t, 1.f); rt = adf * (h * frsqrt_(h)); }
    else if (adf < ab) { float t = adf * frcp_(ab); float h = fmaf(t, t, 1.f); rt = ab  * (h * frsqrt_(h)); }
    else               rt = ab * 1.41421356237309515f;
    int sgn1;
    if (sm < 0.f)      { *rt1 = 0.5f * (sm - rt); sgn1 = -1;
                         float ri = frcp_(*rt1);
                         *rt2 = (acmx * ri) * acmn - (b * ri) * b; }
    else if (sm > 0.f) { *rt1 = 0.5f * (sm + rt); sgn1 = 1;
                         float ri = frcp_(*rt1);
                         *rt2 = (acmx * ri) * acmn - (b * ri) * b; }
    else               { *rt1 = 0.5f * rt; *rt2 = -0.5f * rt; sgn1 = 1; }
    float cs; int sgn2;
    if (df >= 0.f) { cs = df + rt; sgn2 = 1; }
    else           { cs = df - rt; sgn2 = -1; }
    float acs = fabsf(cs), c1, s1;
    if (acs > ab) { float ct = -tb * frcp_(cs); s1 = frsqrt_(fmaf(ct, ct, 1.f)); c1 = ct * s1; }
    else {
        if (ab == 0.f) { c1 = 1.f; s1 = 0.f; }
        else { float tn = -cs * frcp_(tb); c1 = frsqrt_(fmaf(tn, tn, 1.f)); s1 = tn * c1; }
    }
    if (sgn1 == sgn2) { float t = c1; c1 = -s1; s1 = t; }
    *cs1o = c1; *sn1o = s1;
}

// Predicated register-array access (1-based index); keeps arrays in registers.
__device__ __forceinline__ float rget10(const float (&a)[10], int k1) {
    float v = a[0];
#pragma unroll
    for (int k = 2; k <= 10; k++) if (k1 == k) v = a[k - 1];
    return v;
}
__device__ __forceinline__ void rset10(float (&a)[10], int k1, float v) {
#pragma unroll
    for (int k = 1; k <= 10; k++) if (k1 == k) a[k - 1] = v;
}

// ---------------------------------------------------------------------------
// Kernel 2: parallel reduce -> fp32 gram -> register-resident eigensolver with
// approx div/sqrt (same LAPACK branch structure) -> MLP.
// ---------------------------------------------------------------------------
__global__ __launch_bounds__(512, 1)
void finish_kernel(const float* __restrict__ W1, const float* __restrict__ b1,
                   const float* __restrict__ W2, const float* __restrict__ b2,
                   float* __restrict__ out)
{
    __shared__ double part[55][8];
    __shared__ float A[10][10];
    __shared__ float Zsh[10][10];
    __shared__ float wsh[10];
    __shared__ float sW1[160], sb1[16], sW2[16], sb2[1];

    int t = threadIdx.x;

    // ---- preload MLP weights (threads 440..471) ----
    if (t >= 440 && t < 472) {
        int k = t - 440;
#pragma unroll
        for (int r = 0; r < 5; r++) sW1[k * 5 + r] = W1[k * 5 + r];
        if (k < 16) { sb1[k] = b1[k]; sW2[k] = W2[k]; }
        if (k == 0) sb2[0] = b2[0];
    }

    // ---- parallel deterministic double reduction: 55 entries x 8 partitions ----
    if (t < 440) {
        int e = t >> 3, q = t & 7;
        int b0 = q * (NBLK / 8);               // 296 blocks per partition
        double a0 = 0.0, a1 = 0.0, a2 = 0.0, a3 = 0.0;
        for (int b = 0; b < NBLK / 8; b += 4) {
            a0 += (double)g_part[b0 + b + 0][e];
            a1 += (double)g_part[b0 + b + 1][e];
            a2 += (double)g_part[b0 + b + 2][e];
            a3 += (double)g_part[b0 + b + 3][e];
        }
        part[e][q] = (a0 + a1) + (a2 + a3);
    }
    __syncthreads();
    if (t < 55) {
        double s = 0.0;
#pragma unroll
        for (int q = 0; q < 8; q++) s += part[t][q];   // fixed order
        int i = 0, rem = t;
        while (rem >= 10 - i) { rem -= 10 - i; i++; }
        int j = i + rem;
        float fv = (float)s;
        A[i][j] = fv; A[j][i] = fv;
    }
    __syncthreads();
    if (t >= 32) return;
    const unsigned M = 0x3ffu;
    int lane = t;
    if (lane >= 10) return;

    // =======================================================================
    // ssytd2 (UPLO='L'), lane-parallel; approx div/sqrt.
    // =======================================================================
    float dreg[10], ereg[10], wcr[10], wsr[10], taul[9];
#pragma unroll
    for (int ii = 0; ii < 9; ii++) {
        __syncwarp(M);
        float alpha = A[ii + 1][ii];
        float xn2 = 0.f;
#pragma unroll
        for (int r2 = ii + 2; r2 < 10; r2++) xn2 += A[r2][ii] * A[r2][ii];
        float xnorm = fsqrt_(xn2);
        float taui;
        if (xnorm == 0.f) {
            taui = 0.f;
            ereg[ii] = alpha;
        } else {
            float h2 = fmaf(alpha, alpha, xn2);
            float beta = -signf_(h2 * frsqrt_(h2), alpha);
            taui = (beta - alpha) * frcp_(beta);
            float sc = frcp_(alpha - beta);
            ereg[ii] = beta;
            __syncwarp(M);                       // all lanes done reading col ii
            if (lane >= ii + 2) A[lane][ii] *= sc;
            if (lane == ii + 1) A[ii + 1][ii] = 1.f;
            __syncwarp(M);
            if (lane >= ii + 1) {
                float s = 0.f;
#pragma unroll
                for (int c2 = ii + 1; c2 < 10; c2++) {
                    float av = (lane >= c2) ? A[lane][c2] : A[c2][lane];
                    s += av * A[c2][ii];
                }
                wsh[lane] = taui * s;
            }
            __syncwarp(M);
            float dot = 0.f;
#pragma unroll
            for (int r2 = ii + 1; r2 < 10; r2++) dot += wsh[r2] * A[r2][ii];
            float alw = -0.5f * taui * dot;
            __syncwarp(M);
            if (lane >= ii + 1) wsh[lane] += alw * A[lane][ii];
            __syncwarp(M);
            if (lane >= ii + 1) {
                for (int c2 = ii + 1; c2 <= lane; c2++)
                    A[lane][c2] -= A[lane][ii] * wsh[c2] + wsh[lane] * A[c2][ii];
            }
            __syncwarp(M);
            if (lane == ii + 1) A[ii + 1][ii] = ereg[ii];
        }
        taul[ii] = taui;
    }
    __syncwarp(M);
#pragma unroll
    for (int k = 0; k < 10; k++) dreg[k] = A[k][k];

    // =======================================================================
    // Q = H(1)..H(n-1): lane j owns column j.
    // =======================================================================
    float qc[10];
#pragma unroll
    for (int r2 = 0; r2 < 10; r2++) qc[r2] = (r2 == lane) ? 1.f : 0.f;
#pragma unroll
    for (int ii = 8; ii >= 0; ii--) {
        float taui = taul[ii];
        if (taui != 0.f) {
            float s = 0.f;
#pragma unroll
            for (int r2 = 0; r2 < 10; r2++) {
                if (r2 == ii + 1)      s += qc[r2];
                else if (r2 >= ii + 2) s += A[r2][ii] * qc[r2];
            }
            s *= taui;
#pragma unroll
            for (int r2 = 0; r2 < 10; r2++) {
                if (r2 == ii + 1)      qc[r2] -= s;
                else if (r2 >= ii + 2) qc[r2] -= A[r2][ii] * s;
            }
        }
    }
#pragma unroll
    for (int r2 = 0; r2 < 10; r2++) Zsh[r2][lane] = qc[r2];
    __syncwarp(M);
    float z[10];
#pragma unroll
    for (int c2 = 0; c2 < 10; c2++) z[c2] = Zsh[lane][c2];

    // =======================================================================
    // ssteqr ('V'), register-resident, approx arithmetic, LAPACK structure.
    // =======================================================================
    {
    const float EPS    = 5.9604645e-08f;
    const float EPS2   = EPS * EPS;
    const float SAFMIN = 1.1754944e-38f;
    int n = 10, nmaxit = n * 30, jtot = 0;
    int l1 = 1, l = 0, lsv, lend, lendsv, m;
    float p, g, r, c, s, f, b, rt1, rt2;

L10:
    if (l1 > n) goto L160;
    if (l1 > 1) rset10(ereg, l1 - 1, 0.f);
    if (l1 <= n - 1) {
        int msel = n; bool fnd = false;
#pragma unroll
        for (int mm = 1; mm <= 9; mm++) {
            if (!fnd && mm >= l1) {
                float tst = fabsf(ereg[mm - 1]);
                if (tst == 0.f) { msel = mm; fnd = true; }
                else {
                    float prod = fabsf(dreg[mm - 1]) * fabsf(dreg[mm]);
                    if (tst <= fsqrt_(prod) * EPS) {
                        ereg[mm - 1] = 0.f; msel = mm; fnd = true;
                    }
                }
            }
        }
        m = msel;
    } else m = n;
// L30:
    l = l1; lsv = l; lend = m; lendsv = lend; l1 = m + 1;
    if (lend == l) goto L10;
    if (fabsf(rget10(dreg, lend)) < fabsf(rget10(dreg, l))) { lend = lsv; l = lendsv; }
    if (lend > l) goto L40; else goto L90;

    // ============ QL iteration ============
L40:
    if (l != lend) {
        int msel = lend; bool fnd = false;
#pragma unroll
        for (int mm = 1; mm <= 9; mm++) {
            if (!fnd && mm >= l && mm <= lend - 1) {
                float tst = ereg[mm - 1] * ereg[mm - 1];
                if (tst <= EPS2 * fabsf(dreg[mm - 1]) * fabsf(dreg[mm]) + SAFMIN) {
                    msel = mm; fnd = true;
                }
            }
        }
        m = msel;
    } else m = lend;
    if (m < lend) rset10(ereg, m, 0.f);
    p = rget10(dreg, l);
    if (m == l) goto L80;
    if (m == l + 1) {
        slaev2_(rget10(dreg, l), rget10(ereg, l), rget10(dreg, l + 1), &rt1, &rt2, &c, &s);
#pragma unroll
        for (int jj = 0; jj < 9; jj++) if (jj == l - 1) {
            float tmp = z[jj + 1];
            z[jj + 1] = c * tmp - s * z[jj];
            z[jj]     = s * tmp + c * z[jj];
        }
        rset10(dreg, l, rt1); rset10(dreg, l + 1, rt2); rset10(ereg, l, 0.f);
        l += 2;
        if (l <= lend) goto L40;
        goto L140;
    }
    if (jtot == nmaxit) goto L140;
    jtot++;
    {
        float el = rget10(ereg, l);
        g = (rget10(dreg, l + 1) - p) * (0.5f * frcp_(el));
        r = slapy2_1_(g);
        g = rget10(dreg, m) - p + el * frcp_(g + signf_(r, g));
    }
    s = 1.f; c = 1.f; p = 0.f;
#pragma unroll
    for (int i = 9; i >= 1; i--) {
        if (i <= m - 1 && i >= l) {
            f = s * ereg[i - 1]; b = c * ereg[i - 1];
            slartg_(g, f, &c, &s, &r);
            if (i != m - 1) ereg[i] = r;
            g = dreg[i] - p;
            r = (dreg[i - 1] - g) * s + 2.f * c * b;
            p = s * r;
            dreg[i] = g + p;
            g = c * r - b;
            wcr[i - 1] = c; wsr[i - 1] = -s;
        }
    }
#pragma unroll
    for (int jj = 8; jj >= 0; jj--) {
        if (jj >= l - 1 && jj <= m - 2) {
            float ct = wcr[jj], st = wsr[jj];
            float tmp = z[jj + 1];
            z[jj + 1] = ct * tmp - st * z[jj];
            z[jj]     = st * tmp + ct * z[jj];
        }
    }
    rset10(dreg, l, rget10(dreg, l) - p);
    rset10(ereg, l, g);
    goto L40;
L80:
    rset10(dreg, l, p);
    l++;
    if (l <= lend) goto L40;
    goto L140;

    // ============ QR iteration ============
L90:
    if (l != lend) {
        int msel = lend; bool fnd = false;
#pragma unroll
        for (int mm = 10; mm >= 2; mm--) {
            if (!fnd && mm <= l && mm >= lend + 1) {
                float tst = ereg[mm - 2] * ereg[mm - 2];
                if (tst <= EPS2 * fabsf(dreg[mm - 1]) * fabsf(dreg[mm - 2]) + SAFMIN) {
                    msel = mm; fnd = true;
                }
            }
        }
        m = msel;
    } else m = lend;
    if (m > lend) rset10(ereg, m - 1, 0.f);
    p = rget10(dreg, l);
    if (m == l) goto L130;
    if (m == l - 1) {
        slaev2_(rget10(dreg, l - 1), rget10(ereg, l - 1), rget10(dreg, l), &rt1, &rt2, &c, &s);
#pragma unroll
        for (int jj = 0; jj < 9; jj++) if (jj == l - 2) {
            float tmp = z[jj + 1];
            z[jj + 1] = c * tmp - s * z[jj];
            z[jj]     = s * tmp + c * z[jj];
        }
        rset10(dreg, l - 1, rt1); rset10(dreg, l, rt2); rset10(ereg, l - 1, 0.f);
        l -= 2;
        if (l >= lend) goto L90;
        goto L140;
    }
    if (jtot == nmaxit) goto L140;
    jtot++;
    {
        float el = rget10(ereg, l - 1);
        g = (rget10(dreg, l - 1) - p) * (0.5f * frcp_(el));
        r = slapy2_1_(g);
        g = rget10(dreg, m) - p + el * frcp_(g + signf_(r, g));
    }
    s = 1.f; c = 1.f; p = 0.f;
#pragma unroll
    for (int i = 1; i <= 9; i++) {
        if (i >= m && i <= l - 1) {
            f = s * ereg[i - 1]; b = c * ereg[i - 1];
            slartg_(g, f, &c, &s, &r);
            if (i >= 2) { if (i != m) ereg[i - 2] = r; }
            g = dreg[i - 1] - p;
            r = (dreg[i] - g) * s + 2.f * c * b;
            p = s * r;
            dreg[i - 1] = g + p;
            g = c * r - b;
            wcr[i - 1] = c; wsr[i - 1] = s;
        }
    }
#pragma unroll
    for (int jj = 0; jj <= 8; jj++) {
        if (jj >= m - 1 && jj <= l - 2) {
            float ct = wcr[jj], st = wsr[jj];
            float tmp = z[jj + 1];
            z[jj + 1] = ct * tmp - st * z[jj];
            z[jj]     = st * tmp + ct * z[jj];
        }
    }
    rset10(dreg, l, rget10(dreg, l) - p);
    rset10(ereg, l - 1, g);
    goto L90;
L130:
    rset10(dreg, l, p);
    l--;
    if (l >= lend) goto L90;
    goto L140;

L140:
    if (jtot < nmaxit) goto L10;
    goto L160;

L160:
    // LAPACK ascending selection sort with column swaps.
    for (int ii2 = 2; ii2 <= n; ii2++) {
        int i = ii2 - 1, k = i;
        float pp = rget10(dreg, i);
#pragma unroll
        for (int j = 2; j <= 10; j++) {
            if (j >= ii2) {
                float dj = dreg[j - 1];
                if (dj < pp) { k = j; pp = dj; }
            }
        }
        if (k != i) {
            rset10(dreg, k, rget10(dreg, i));
            rset10(dreg, i, pp);
            float zi = 0.f, zk = 0.f;
#pragma unroll
            for (int cidx = 0; cidx < 10; cidx++) {
                if (cidx == i - 1) zi = z[cidx];
                if (cidx == k - 1) zk = z[cidx];
            }
#pragma unroll
            for (int cidx = 0; cidx < 10; cidx++) {
                if (cidx == i - 1) z[cidx] = zk;
                if (cidx == k - 1) z[cidx] = zi;
            }
        }
    }
    }

    // ---- MLP per-lane: lane i computes output row i ------------------------
    {
        float y2 = sb2[0];
#pragma unroll
        for (int h = 0; h < 16; h++) {
            float a1 = sb1[h];
#pragma unroll
            for (int j = 0; j < 10; j++) a1 = fmaf(z[j], sW1[h * 10 + j], a1);
            a1 = fmaxf(a1, 0.f);
            y2 = fmaf(a1, sW2[h], y2);
        }
        out[lane] = 0.5f * (1.f / (1.f + expf(-y2)) + 1.f);
    }
}

extern "C" void kernel_launch(void* const* d_in, const int* in_sizes, int n_in,
                              void* d_out, int out_size)
{
    const float* x  = (const float*)d_in[0];
    const float* W1 = (const float*)d_in[1];
    const float* b1 = (const float*)d_in[2];
    const float* W2 = (const float*)d_in[3];
    const float* b2 = (const float*)d_in[4];
    int nrows = in_sizes[0] / 10;
    int units = nrows / 2;
    gram_kernel<<<NBLK, TPB>>>(x, units, nrows);
    finish_kernel<<<1, 512>>>(W1, b1, W2, b2, (float*)d_out);
}

// round 7
// speedup vs baseline: 2.3644x; 1.7731x over previous
#include <cuda_runtime.h>
#include <math.h>

#define NBLK 2368
#define TPB  128

// Transposed per-block partials: entry-major so the reduce kernel reads
// each entry's 2368 partials as one contiguous, coalesced row.
__device__ float g_part_T[55][NBLK];
__device__ float g_gram[55];

__device__ __forceinline__ constexpr int tri_idx(int i, int j) {
    return i * 10 - (i * (i + 1)) / 2 + j;   // i <= j
}

// ---------------------------------------------------------------------------
// Kernel 1: deterministic Gram partial reduction (FFMA2 packed accumulate).
// ---------------------------------------------------------------------------
__global__ __launch_bounds__(TPB, 3) void gram_kernel(const float* __restrict__ x,
                                                      int units, int nrows)
{
    const float4* __restrict__ xv = (const float4*)x;
    unsigned long long acc2[55];
#pragma unroll
    for (int k = 0; k < 55; k++) acc2[k] = 0ull;   // {+0.f, +0.f}

    int tid = blockIdx.x * TPB + threadIdx.x;
    const int stride = NBLK * TPB;
    for (int p = tid; p < units; p += stride) {
        float v[20];
        int base = 5 * p;
        float4 q;
        q = xv[base + 0]; v[0]  = q.x; v[1]  = q.y; v[2]  = q.z; v[3]  = q.w;
        q = xv[base + 1]; v[4]  = q.x; v[5]  = q.y; v[6]  = q.z; v[7]  = q.w;
        q = xv[base + 2]; v[8]  = q.x; v[9]  = q.y; v[10] = q.z; v[11] = q.w;
        q = xv[base + 3]; v[12] = q.x; v[13] = q.y; v[14] = q.z; v[15] = q.w;
        q = xv[base + 4]; v[16] = q.x; v[17] = q.y; v[18] = q.z; v[19] = q.w;
        unsigned long long vp[10];
#pragma unroll
        for (int i = 0; i < 10; i++)
            asm("mov.b64 %0, {%1, %2};" : "=l"(vp[i]) : "f"(v[i]), "f"(v[10 + i]));
#pragma unroll
        for (int i = 0; i < 10; i++)
#pragma unroll
            for (int j = i; j < 10; j++)
                asm("fma.rn.f32x2 %0, %1, %2, %0;"
                    : "+l"(acc2[tri_idx(i, j)]) : "l"(vp[i]), "l"(vp[j]));
    }

    float acc[55];
#pragma unroll
    for (int k = 0; k < 55; k++) {
        float lo, hi;
        asm("mov.b64 {%0, %1}, %2;" : "=f"(lo), "=f"(hi) : "l"(acc2[k]));
        acc[k] = lo + hi;
    }

    if (tid == 0 && (nrows & 1)) {
        const float* last = x + (size_t)(nrows - 1) * 10;
        float v[10];
#pragma unroll
        for (int i = 0; i < 10; i++) v[i] = last[i];
#pragma unroll
        for (int i = 0; i < 10; i++)
#pragma unroll
            for (int j = i; j < 10; j++)
                acc[tri_idx(i, j)] = fmaf(v[i], v[j], acc[tri_idx(i, j)]);
    }

#pragma unroll
    for (int k = 0; k < 55; k++) {
#pragma unroll
        for (int off = 16; off > 0; off >>= 1)
            acc[k] += __shfl_down_sync(0xffffffffu, acc[k], off);
    }
    __shared__ float red[TPB / 32][55];
    int lane = threadIdx.x & 31, wid = threadIdx.x >> 5;
    if (lane == 0) {
#pragma unroll
        for (int k = 0; k < 55; k++) red[wid][k] = acc[k];
    }
    __syncthreads();
    if (threadIdx.x < 55) {
        float s = 0.f;
#pragma unroll
        for (int w = 0; w < TPB / 32; w++) s += red[w][threadIdx.x];
        g_part_T[threadIdx.x][blockIdx.x] = s;
    }
}

// ---------------------------------------------------------------------------
// Kernel 2: per-entry coalesced deterministic reduction.
// Block e sums g_part_T[e][0..NBLK) in double: fixed strided partition per
// thread + fixed binary tree => bit-stable.
// ---------------------------------------------------------------------------
__global__ __launch_bounds__(256, 1) void reduce_kernel()
{
    __shared__ double sh[256];
    int e = blockIdx.x, q = threadIdx.x;
    double s = 0.0;
    for (int k = q; k < NBLK; k += 256)
        s += (double)g_part_T[e][k];
    sh[q] = s;
    __syncthreads();
#pragma unroll
    for (int off = 128; off > 0; off >>= 1) {
        if (q < off) sh[q] += sh[q + off];
        __syncthreads();
    }
    if (q == 0) g_gram[e] = (float)sh[0];
}

// ---------------------------------------------------------------------------
// Fast approx primitives (MUFU; <=2^-23 rel err).
// ---------------------------------------------------------------------------
__device__ __forceinline__ float frcp_(float x) {
    float r; asm("rcp.approx.ftz.f32 %0, %1;" : "=f"(r) : "f"(x)); return r;
}
__device__ __forceinline__ float frsqrt_(float x) {
    float r; asm("rsqrt.approx.ftz.f32 %0, %1;" : "=f"(r) : "f"(x)); return r;
}
__device__ __forceinline__ float fsqrt_(float x) {          // x >= 0
    return (x > 0.f) ? x * frsqrt_(x) : 0.f;
}

__device__ __forceinline__ float signf_(float a, float b) {
    return b >= 0.f ? fabsf(a) : -fabsf(a);
}
__device__ __forceinline__ float slapy2_1_(float g) {
    float t = fmaf(g, g, 1.f);
    return t * frsqrt_(t);
}
// Branchless Givens (LAPACK sign convention), rsqrt-based.
__device__ __forceinline__ void slartg_(float f, float g, float* cs, float* sn, float* r) {
    float f2   = fmaf(f, f, g * g);
    float rinv = frsqrt_(f2);
    float d    = f2 * rinv;
    float sgn  = (f >= 0.f) ? 1.f : -1.f;
    float cs0  = fabsf(f) * rinv;
    float sn0  = g * rinv * sgn;
    float r0   = sgn * d;
    bool gz = (g == 0.f), fz = (f == 0.f);
    *cs = gz ? 1.f : (fz ? 0.f                      : cs0);
    *sn = gz ? 0.f : (fz ? ((g >= 0.f) ? 1.f : -1.f): sn0);
    *r  = gz ? f   : (fz ? fabsf(g)                 : r0);
}
__device__ __forceinline__ void slaev2_(float a, float b, float cc,
                        float* rt1, float* rt2, float* cs1o, float* sn1o) {
    float sm = a + cc, df = a - cc;
    float adf = fabsf(df), tb = b + b, ab = fabsf(tb);
    float acmx, acmn;
    if (fabsf(a) > fabsf(cc)) { acmx = a;  acmn = cc; }
    else                      { acmx = cc; acmn = a;  }
    float rt;
    if (adf > ab)      { float t = ab * frcp_(adf); float h = fmaf(t, t, 1.f); rt = adf * (h * frsqrt_(h)); }
    else if (adf < ab) { float t = adf * frcp_(ab); float h = fmaf(t, t, 1.f); rt = ab  * (h * frsqrt_(h)); }
    else               rt = ab * 1.41421356237309515f;
    int sgn1;
    if (sm < 0.f)      { *rt1 = 0.5f * (sm - rt); sgn1 = -1;
                         float ri = frcp_(*rt1);
                         *rt2 = (acmx * ri) * acmn - (b * ri) * b; }
    else if (sm > 0.f) { *rt1 = 0.5f * (sm + rt); sgn1 = 1;
                         float ri = frcp_(*rt1);
                         *rt2 = (acmx * ri) * acmn - (b * ri) * b; }
    else               { *rt1 = 0.5f * rt; *rt2 = -0.5f * rt; sgn1 = 1; }
    float cs; int sgn2;
    if (df >= 0.f) { cs = df + rt; sgn2 = 1; }
    else           { cs = df - rt; sgn2 = -1; }
    float acs = fabsf(cs), c1, s1;
    if (acs > ab) { float ct = -tb * frcp_(cs); s1 = frsqrt_(fmaf(ct, ct, 1.f)); c1 = ct * s1; }
    else {
        if (ab == 0.f) { c1 = 1.f; s1 = 0.f; }
        else { float tn = -cs * frcp_(tb); c1 = frsqrt_(fmaf(tn, tn, 1.f)); s1 = tn * c1; }
    }
    if (sgn1 == sgn2) { float t = c1; c1 = -s1; s1 = t; }
    *cs1o = c1; *sn1o = s1;
}

// Predicated register-array access (1-based index); keeps arrays in registers.
__device__ __forceinline__ float rget10(const float (&a)[10], int k1) {
    float v = a[0];
#pragma unroll
    for (int k = 2; k <= 10; k++) if (k1 == k) v = a[k - 1];
    return v;
}
__device__ __forceinline__ void rset10(float (&a)[10], int k1, float v) {
#pragma unroll
    for (int k = 1; k <= 10; k++) if (k1 == k) a[k - 1] = v;
}

// ---------------------------------------------------------------------------
// Kernel 3 (one warp): gram -> register-resident eigensolver -> MLP.
// ---------------------------------------------------------------------------
__global__ __launch_bounds__(32, 1)
void finish_kernel(const float* __restrict__ W1, const float* __restrict__ b1,
                   const float* __restrict__ W2, const float* __restrict__ b2,
                   float* __restrict__ out)
{
    __shared__ float A[10][10];
    __shared__ float Zsh[10][10];
    __shared__ float wsh[10];
    __shared__ float sW1[160], sb1[16], sW2[16], sb2[1];

    int lane = threadIdx.x;

    // ---- preload weights + gram (one warp, strided) ----
    for (int idx = lane; idx < 160; idx += 32) sW1[idx] = W1[idx];
    if (lane < 16) { sb1[lane] = b1[lane]; sW2[lane] = W2[lane]; }
    if (lane == 0) sb2[0] = b2[0];
    for (int idx = lane; idx < 55; idx += 32) {
        int i = 0, rem = idx;
        while (rem >= 10 - i) { rem -= 10 - i; i++; }
        int j = i + rem;
        float fv = g_gram[idx];
        A[i][j] = fv; A[j][i] = fv;
    }
    __syncwarp();
    const unsigned M = 0x3ffu;
    if (lane >= 10) return;

    // =======================================================================
    // ssytd2 (UPLO='L'), lane-parallel; approx div/sqrt.
    // =======================================================================
    float dreg[10], ereg[10], wcr[10], wsr[10], taul[9];
#pragma unroll
    for (int ii = 0; ii < 9; ii++) {
        __syncwarp(M);
        float alpha = A[ii + 1][ii];
        float xn2 = 0.f;
#pragma unroll
        for (int r2 = ii + 2; r2 < 10; r2++) xn2 += A[r2][ii] * A[r2][ii];
        float xnorm = fsqrt_(xn2);
        float taui;
        if (xnorm == 0.f) {
            taui = 0.f;
            ereg[ii] = alpha;
        } else {
            float h2 = fmaf(alpha, alpha, xn2);
            float beta = -signf_(h2 * frsqrt_(h2), alpha);
            taui = (beta - alpha) * frcp_(beta);
            float sc = frcp_(alpha - beta);
            ereg[ii] = beta;
            __syncwarp(M);                       // all lanes done reading col ii
            if (lane >= ii + 2) A[lane][ii] *= sc;
            if (lane == ii + 1) A[ii + 1][ii] = 1.f;
            __syncwarp(M);
            if (lane >= ii + 1) {
                float s = 0.f;
#pragma unroll
                for (int c2 = ii + 1; c2 < 10; c2++) {
                    float av = (lane >= c2) ? A[lane][c2] : A[c2][lane];
                    s += av * A[c2][ii];
                }
                wsh[lane] = taui * s;
            }
            __syncwarp(M);
            float dot = 0.f;
#pragma unroll
            for (int r2 = ii + 1; r2 < 10; r2++) dot += wsh[r2] * A[r2][ii];
            float alw = -0.5f * taui * dot;
            __syncwarp(M);
            if (lane >= ii + 1) wsh[lane] += alw * A[lane][ii];
            __syncwarp(M);
            if (lane >= ii + 1) {
                for (int c2 = ii + 1; c2 <= lane; c2++)
                    A[lane][c2] -= A[lane][ii] * wsh[c2] + wsh[lane] * A[c2][ii];
            }
            __syncwarp(M);
            if (lane == ii + 1) A[ii + 1][ii] = ereg[ii];
        }
        taul[ii] = taui;
    }
    __syncwarp(M);
#pragma unroll
    for (int k = 0; k < 10; k++) dreg[k] = A[k][k];

    // =======================================================================
    // Q = H(1)..H(n-1): lane j owns column j.
    // =======================================================================
    float qc[10];
#pragma unroll
    for (int r2 = 0; r2 < 10; r2++) qc[r2] = (r2 == lane) ? 1.f : 0.f;
#pragma unroll
    for (int ii = 8; ii >= 0; ii--) {
        float taui = taul[ii];
        if (taui != 0.f) {
            float s = 0.f;
#pragma unroll
            for (int r2 = 0; r2 < 10; r2++) {
                if (r2 == ii + 1)      s += qc[r2];
                else if (r2 >= ii + 2) s += A[r2][ii] * qc[r2];
            }
            s *= taui;
#pragma unroll
            for (int r2 = 0; r2 < 10; r2++) {
                if (r2 == ii + 1)      qc[r2] -= s;
                else if (r2 >= ii + 2) qc[r2] -= A[r2][ii] * s;
            }
        }
    }
#pragma unroll
    for (int r2 = 0; r2 < 10; r2++) Zsh[r2][lane] = qc[r2];
    __syncwarp(M);
    float z[10];
#pragma unroll
    for (int c2 = 0; c2 < 10; c2++) z[c2] = Zsh[lane][c2];

    // =======================================================================
    // ssteqr ('V'), register-resident, approx arithmetic, LAPACK structure.
    // =======================================================================
    {
    const float EPS    = 5.9604645e-08f;
    const float EPS2   = EPS * EPS;
    const float SAFMIN = 1.1754944e-38f;
    int n = 10, nmaxit = n * 30, jtot = 0;
    int l1 = 1, l = 0, lsv, lend, lendsv, m;
    float p, g, r, c, s, f, b, rt1, rt2;

L10:
    if (l1 > n) goto L160;
    if (l1 > 1) rset10(ereg, l1 - 1, 0.f);
    if (l1 <= n - 1) {
        int msel = n; bool fnd = false;
#pragma unroll
        for (int mm = 1; mm <= 9; mm++) {
            if (!fnd && mm >= l1) {
                float tst = fabsf(ereg[mm - 1]);
                if (tst == 0.f) { msel = mm; fnd = true; }
                else {
                    float prod = fabsf(dreg[mm - 1]) * fabsf(dreg[mm]);
                    if (tst <= fsqrt_(prod) * EPS) {
                        ereg[mm - 1] = 0.f; msel = mm; fnd = true;
                    }
                }
            }
        }
        m = msel;
    } else m = n;
// L30:
    l = l1; lsv = l; lend = m; lendsv = lend; l1 = m + 1;
    if (lend == l) goto L10;
    if (fabsf(rget10(dreg, lend)) < fabsf(rget10(dreg, l))) { lend = lsv; l = lendsv; }
    if (lend > l) goto L40; else goto L90;

    // ============ QL iteration ============
L40:
    if (l != lend) {
        int msel = lend; bool fnd = false;
#pragma unroll
        for (int mm = 1; mm <= 9; mm++) {
            if (!fnd && mm >= l && mm <= lend - 1) {
                float tst = ereg[mm - 1] * ereg[mm - 1];
                if (tst <= EPS2 * fabsf(dreg[mm - 1]) * fabsf(dreg[mm]) + SAFMIN) {
                    msel = mm; fnd = true;
                }
            }
        }
        m = msel;
    } else m = lend;
    if (m < lend) rset10(ereg, m, 0.f);
    p = rget10(dreg, l);
    if (m == l) goto L80;
    if (m == l + 1) {
        slaev2_(rget10(dreg, l), rget10(ereg, l), rget10(dreg, l + 1), &rt1, &rt2, &c, &s);
#pragma unroll
        for (int jj = 0; jj < 9; jj++) if (jj == l - 1) {
            float tmp = z[jj + 1];
            z[jj + 1] = c * tmp - s * z[jj];
            z[jj]     = s * tmp + c * z[jj];
        }
        rset10(dreg, l, rt1); rset10(dreg, l + 1, rt2); rset10(ereg, l, 0.f);
        l += 2;
        if (l <= lend) goto L40;
        goto L140;
    }
    if (jtot == nmaxit) goto L140;
    jtot++;
    {
        float el = rget10(ereg, l);
        g = (rget10(dreg, l + 1) - p) * (0.5f * frcp_(el));
        r = slapy2_1_(g);
        g = rget10(dreg, m) - p + el * frcp_(g + signf_(r, g));
    }
    s = 1.f; c = 1.f; p = 0.f;
#pragma unroll
    for (int i = 9; i >= 1; i--) {
        if (i <= m - 1 && i >= l) {
            f = s * ereg[i - 1]; b = c * ereg[i - 1];
            slartg_(g, f, &c, &s, &r);
            if (i != m - 1) ereg[i] = r;
            g = dreg[i] - p;
            r = (dreg[i - 1] - g) * s + 2.f * c * b;
            p = s * r;
            dreg[i] = g + p;
            g = c * r - b;
            wcr[i - 1] = c; wsr[i - 1] = -s;
        }
    }
#pragma unroll
    for (int jj = 8; jj >= 0; jj--) {
        if (jj >= l - 1 && jj <= m - 2) {
            float ct = wcr[jj], st = wsr[jj];
            float tmp = z[jj + 1];
            z[jj + 1] = ct * tmp - st * z[jj];
            z[jj]     = st * tmp + ct * z[jj];
        }
    }
    rset10(dreg, l, rget10(dreg, l) - p);
    rset10(ereg, l, g);
    goto L40;
L80:
    rset10(dreg, l, p);
    l++;
    if (l <= lend) goto L40;
    goto L140;

    // ============ QR iteration ============
L90:
    if (l != lend) {
        int msel = lend; bool fnd = false;
#pragma unroll
        for (int mm = 10; mm >= 2; mm--) {
            if (!fnd && mm <= l && mm >= lend + 1) {
                float tst = ereg[mm - 2] * ereg[mm - 2];
                if (tst <= EPS2 * fabsf(dreg[mm - 1]) * fabsf(dreg[mm - 2]) + SAFMIN) {
                    msel = mm; fnd = true;
                }
            }
        }
        m = msel;
    } else m = lend;
    if (m > lend) rset10(ereg, m - 1, 0.f);
    p = rget10(dreg, l);
    if (m == l) goto L130;
    if (m == l - 1) {
        slaev2_(rget10(dreg, l - 1), rget10(ereg, l - 1), rget10(dreg, l), &rt1, &rt2, &c, &s);
#pragma unroll
        for (int jj = 0; jj < 9; jj++) if (jj == l - 2) {
            float tmp = z[jj + 1];
            z[jj + 1] = c * tmp - s * z[jj];
            z[jj]     = s * tmp + c * z[jj];
        }
        rset10(dreg, l - 1, rt1); rset10(dreg, l, rt2); rset10(ereg, l - 1, 0.f);
        l -= 2;
        if (l >= lend) goto L90;
        goto L140;
    }
    if (jtot == nmaxit) goto L140;
    jtot++;
    {
        float el = rget10(ereg, l - 1);
        g = (rget10(dreg, l - 1) - p) * (0.5f * frcp_(el));
        r = slapy2_1_(g);
        g = rget10(dreg, m) - p + el * frcp_(g + signf_(r, g));
    }
    s = 1.f; c = 1.f; p = 0.f;
#pragma unroll
    for (int i = 1; i <= 9; i++) {
        if (i >= m && i <= l - 1) {
            f = s * ereg[i - 1]; b = c * ereg[i - 1];
            slartg_(g, f, &c, &s, &r);
            if (i >= 2) { if (i != m) ereg[i - 2] = r; }
            g = dreg[i - 1] - p;
            r = (dreg[i] - g) * s + 2.f * c * b;
            p = s * r;
            dreg[i - 1] = g + p;
            g = c * r - b;
            wcr[i - 1] = c; wsr[i - 1] = s;
        }
    }
#pragma unroll
    for (int jj = 0; jj <= 8; jj++) {
        if (jj >= m - 1 && jj <= l - 2) {
            float ct = wcr[jj], st = wsr[jj];
            float tmp = z[jj + 1];
            z[jj + 1] = ct * tmp - st * z[jj];
            z[jj]     = st * tmp + ct * z[jj];
        }
    }
    rset10(dreg, l, rget10(dreg, l) - p);
    rset10(ereg, l - 1, g);
    goto L90;
L130:
    rset10(dreg, l, p);
    l--;
    if (l >= lend) goto L90;
    goto L140;

L140:
    if (jtot < nmaxit) goto L10;
    goto L160;

L160:
    // LAPACK ascending selection sort with column swaps.
    for (int ii2 = 2; ii2 <= n; ii2++) {
        int i = ii2 - 1, k = i;
        float pp = rget10(dreg, i);
#pragma unroll
        for (int j = 2; j <= 10; j++) {
            if (j >= ii2) {
                float dj = dreg[j - 1];
                if (dj < pp) { k = j; pp = dj; }
            }
        }
        if (k != i) {
            rset10(dreg, k, rget10(dreg, i));
            rset10(dreg, i, pp);
            float zi = 0.f, zk = 0.f;
#pragma unroll
            for (int cidx = 0; cidx < 10; cidx++) {
                if (cidx == i - 1) zi = z[cidx];
                if (cidx == k - 1) zk = z[cidx];
            }
#pragma unroll
            for (int cidx = 0; cidx < 10; cidx++) {
                if (cidx == i - 1) z[cidx] = zk;
                if (cidx == k - 1) z[cidx] = zi;
            }
        }
    }
    }

    // ---- MLP per-lane: lane i computes output row i ------------------------
    {
        float y2 = sb2[0];
#pragma unroll
        for (int h = 0; h < 16; h++) {
            float a1 = sb1[h];
#pragma unroll
            for (int j = 0; j < 10; j++) a1 = fmaf(z[j], sW1[h * 10 + j], a1);
            a1 = fmaxf(a1, 0.f);
            y2 = fmaf(a1, sW2[h], y2);
        }
        out[lane] = 0.5f * (1.f / (1.f + expf(-y2)) + 1.f);
    }
}

extern "C" void kernel_launch(void* const* d_in, const int* in_sizes, int n_in,
                              void* d_out, int out_size)
{
    const float* x  = (const float*)d_in[0];
    const float* W1 = (const float*)d_in[1];
    const float* b1 = (const float*)d_in[2];
    const float* W2 = (const float*)d_in[3];
    const float* b2 = (const float*)d_in[4];
    int nrows = in_sizes[0] / 10;
    int units = nrows / 2;
    gram_kernel<<<NBLK, TPB>>>(x, units, nrows);
    reduce_kernel<<<55, 256>>>();
    finish_kernel<<<1, 32>>>(W1, b1, W2, b2, (float*)d_out);
}

// round 8
// speedup vs baseline: 2.6816x; 1.1341x over previous
#include <cuda_runtime.h>
#include <math.h>

#define NBLK 2368
#define TPB  128

// Transposed per-block partials: entry-major so the reduce kernel reads
// each entry's 2368 partials as one contiguous, coalesced row.
__device__ float g_part_T[55][NBLK];
__device__ float g_gram[55];

__device__ __forceinline__ constexpr int tri_idx(int i, int j) {
    return i * 10 - (i * (i + 1)) / 2 + j;   // i <= j
}

// ---------------------------------------------------------------------------
// Kernel 1: deterministic Gram partial reduction.
// 4-row units (160B = 10 aligned float4 loads, front-batched for MLP=10),
// 55 scalar fp32 accumulators (no packing movs, low register pressure).
// ---------------------------------------------------------------------------
__global__ __launch_bounds__(TPB, 4) void gram_kernel(const float* __restrict__ x,
                                                      int quads, int nrows)
{
    const float4* __restrict__ xv = (const float4*)x;
    float acc[55];
#pragma unroll
    for (int k = 0; k < 55; k++) acc[k] = 0.f;

    int tid = blockIdx.x * TPB + threadIdx.x;
    const int stride = NBLK * TPB;
    for (int p = tid; p < quads; p += stride) {
        float v[40];
        int base = 10 * p;
        // Front-batched loads: 10 independent LDG.128 in flight.
        float4 q0 = xv[base + 0], q1 = xv[base + 1], q2 = xv[base + 2],
               q3 = xv[base + 3], q4 = xv[base + 4], q5 = xv[base + 5],
               q6 = xv[base + 6], q7 = xv[base + 7], q8 = xv[base + 8],
               q9 = xv[base + 9];
        v[0]=q0.x; v[1]=q0.y; v[2]=q0.z; v[3]=q0.w;
        v[4]=q1.x; v[5]=q1.y; v[6]=q1.z; v[7]=q1.w;
        v[8]=q2.x; v[9]=q2.y; v[10]=q2.z; v[11]=q2.w;
        v[12]=q3.x; v[13]=q3.y; v[14]=q3.z; v[15]=q3.w;
        v[16]=q4.x; v[17]=q4.y; v[18]=q4.z; v[19]=q4.w;
        v[20]=q5.x; v[21]=q5.y; v[22]=q5.z; v[23]=q5.w;
        v[24]=q6.x; v[25]=q6.y; v[26]=q6.z; v[27]=q6.w;
        v[28]=q7.x; v[29]=q7.y; v[30]=q7.z; v[31]=q7.w;
        v[32]=q8.x; v[33]=q8.y; v[34]=q8.z; v[35]=q8.w;
        v[36]=q9.x; v[37]=q9.y; v[38]=q9.z; v[39]=q9.w;
#pragma unroll
        for (int r = 0; r < 4; r++)
#pragma unroll
            for (int i = 0; i < 10; i++)
#pragma unroll
                for (int j = i; j < 10; j++)
                    acc[tri_idx(i, j)] =
                        fmaf(v[10 * r + i], v[10 * r + j], acc[tri_idx(i, j)]);
    }

    // Tail rows (nrows % 4), handled by thread 0 (not hit for N=4M).
    if (tid == 0) {
        for (int rr = 4 * quads; rr < nrows; rr++) {
            const float* row = x + (size_t)rr * 10;
            float v[10];
#pragma unroll
            for (int i = 0; i < 10; i++) v[i] = row[i];
#pragma unroll
            for (int i = 0; i < 10; i++)
#pragma unroll
                for (int j = i; j < 10; j++)
                    acc[tri_idx(i, j)] = fmaf(v[i], v[j], acc[tri_idx(i, j)]);
        }
    }

    // Deterministic warp shuffle tree reduce per entry.
#pragma unroll
    for (int k = 0; k < 55; k++) {
#pragma unroll
        for (int off = 16; off > 0; off >>= 1)
            acc[k] += __shfl_down_sync(0xffffffffu, acc[k], off);
    }
    __shared__ float red[TPB / 32][55];
    int lane = threadIdx.x & 31, wid = threadIdx.x >> 5;
    if (lane == 0) {
#pragma unroll
        for (int k = 0; k < 55; k++) red[wid][k] = acc[k];
    }
    __syncthreads();
    if (threadIdx.x < 55) {
        float s = 0.f;
#pragma unroll
        for (int w = 0; w < TPB / 32; w++) s += red[w][threadIdx.x];
        g_part_T[threadIdx.x][blockIdx.x] = s;
    }
}

// ---------------------------------------------------------------------------
// Kernel 2: per-entry coalesced deterministic reduction.
// ---------------------------------------------------------------------------
__global__ __launch_bounds__(256, 1) void reduce_kernel()
{
    __shared__ double sh[256];
    int e = blockIdx.x, q = threadIdx.x;
    double s = 0.0;
    for (int k = q; k < NBLK; k += 256)
        s += (double)g_part_T[e][k];
    sh[q] = s;
    __syncthreads();
#pragma unroll
    for (int off = 128; off > 0; off >>= 1) {
        if (q < off) sh[q] += sh[q + off];
        __syncthreads();
    }
    if (q == 0) g_gram[e] = (float)sh[0];
}

// ---------------------------------------------------------------------------
// Fast approx primitives (MUFU; <=2^-23 rel err).
// ---------------------------------------------------------------------------
__device__ __forceinline__ float frcp_(float x) {
    float r; asm("rcp.approx.ftz.f32 %0, %1;" : "=f"(r) : "f"(x)); return r;
}
__device__ __forceinline__ float frsqrt_(float x) {
    float r; asm("rsqrt.approx.ftz.f32 %0, %1;" : "=f"(r) : "f"(x)); return r;
}
__device__ __forceinline__ float fsqrt_(float x) {          // x >= 0
    return (x > 0.f) ? x * frsqrt_(x) : 0.f;
}

__device__ __forceinline__ float signf_(float a, float b) {
    return b >= 0.f ? fabsf(a) : -fabsf(a);
}
__device__ __forceinline__ float slapy2_1_(float g) {
    float t = fmaf(g, g, 1.f);
    return t * frsqrt_(t);
}
// Branchless Givens (LAPACK sign convention), rsqrt-based.
__device__ __forceinline__ void slartg_(float f, float g, float* cs, float* sn, float* r) {
    float f2   = fmaf(f, f, g * g);
    float rinv = frsqrt_(f2);
    float d    = f2 * rinv;
    float sgn  = (f >= 0.f) ? 1.f : -1.f;
    float cs0  = fabsf(f) * rinv;
    float sn0  = g * rinv * sgn;
    float r0   = sgn * d;
    bool gz = (g == 0.f), fz = (f == 0.f);
    *cs = gz ? 1.f : (fz ? 0.f                      : cs0);
    *sn = gz ? 0.f : (fz ? ((g >= 0.f) ? 1.f : -1.f): sn0);
    *r  = gz ? f   : (fz ? fabsf(g)                 : r0);
}
__device__ __forceinline__ void slaev2_(float a, float b, float cc,
                        float* rt1, float* rt2, float* cs1o, float* sn1o) {
    float sm = a + cc, df = a - cc;
    float adf = fabsf(df), tb = b + b, ab = fabsf(tb);
    float acmx, acmn;
    if (fabsf(a) > fabsf(cc)) { acmx = a;  acmn = cc; }
    else                      { acmx = cc; acmn = a;  }
    float rt;
    if (adf > ab)      { float t = ab * frcp_(adf); float h = fmaf(t, t, 1.f); rt = adf * (h * frsqrt_(h)); }
    else if (adf < ab) { float t = adf * frcp_(ab); float h = fmaf(t, t, 1.f); rt = ab  * (h * frsqrt_(h)); }
    else               rt = ab * 1.41421356237309515f;
    int sgn1;
    if (sm < 0.f)      { *rt1 = 0.5f * (sm - rt); sgn1 = -1;
                         float ri = frcp_(*rt1);
                         *rt2 = (acmx * ri) * acmn - (b * ri) * b; }
    else if (sm > 0.f) { *rt1 = 0.5f * (sm + rt); sgn1 = 1;
                         float ri = frcp_(*rt1);
                         *rt2 = (acmx * ri) * acmn - (b * ri) * b; }
    else               { *rt1 = 0.5f * rt; *rt2 = -0.5f * rt; sgn1 = 1; }
    float cs; int sgn2;
    if (df >= 0.f) { cs = df + rt; sgn2 = 1; }
    else           { cs = df - rt; sgn2 = -1; }
    float acs = fabsf(cs), c1, s1;
    if (acs > ab) { float ct = -tb * frcp_(cs); s1 = frsqrt_(fmaf(ct, ct, 1.f)); c1 = ct * s1; }
    else {
        if (ab == 0.f) { c1 = 1.f; s1 = 0.f; }
        else { float tn = -cs * frcp_(tb); c1 = frsqrt_(fmaf(tn, tn, 1.f)); s1 = tn * c1; }
    }
    if (sgn1 == sgn2) { float t = c1; c1 = -s1; s1 = t; }
    *cs1o = c1; *sn1o = s1;
}

// Predicated register-array access (1-based index); keeps arrays in registers.
__device__ __forceinline__ float rget10(const float (&a)[10], int k1) {
    float v = a[0];
#pragma unroll
    for (int k = 2; k <= 10; k++) if (k1 == k) v = a[k - 1];
    return v;
}
__device__ __forceinline__ void rset10(float (&a)[10], int k1, float v) {
#pragma unroll
    for (int k = 1; k <= 10; k++) if (k1 == k) a[k - 1] = v;
}

// ---------------------------------------------------------------------------
// Kernel 3 (one warp): gram -> register-resident eigensolver -> MLP.
// ---------------------------------------------------------------------------
__global__ __launch_bounds__(32, 1)
void finish_kernel(const float* __restrict__ W1, const float* __restrict__ b1,
                   const float* __restrict__ W2, const float* __restrict__ b2,
                   float* __restrict__ out)
{
    __shared__ float A[10][10];
    __shared__ float Zsh[10][10];
    __shared__ float wsh[10];
    __shared__ float sW1[160], sb1[16], sW2[16], sb2[1];

    int lane = threadIdx.x;

    // ---- preload weights + gram (one warp, strided) ----
    for (int idx = lane; idx < 160; idx += 32) sW1[idx] = W1[idx];
    if (lane < 16) { sb1[lane] = b1[lane]; sW2[lane] = W2[lane]; }
    if (lane == 0) sb2[0] = b2[0];
    for (int idx = lane; idx < 55; idx += 32) {
        int i = 0, rem = idx;
        while (rem >= 10 - i) { rem -= 10 - i; i++; }
        int j = i + rem;
        float fv = g_gram[idx];
        A[i][j] = fv; A[j][i] = fv;
    }
    __syncwarp();
    const unsigned M = 0x3ffu;
    if (lane >= 10) return;

    // =======================================================================
    // ssytd2 (UPLO='L'), lane-parallel; approx div/sqrt.
    // =======================================================================
    float dreg[10], ereg[10], wcr[10], wsr[10], taul[9];
#pragma unroll
    for (int ii = 0; ii < 9; ii++) {
        __syncwarp(M);
        float alpha = A[ii + 1][ii];
        float xn2 = 0.f;
#pragma unroll
        for (int r2 = ii + 2; r2 < 10; r2++) xn2 += A[r2][ii] * A[r2][ii];
        float xnorm = fsqrt_(xn2);
        float taui;
        if (xnorm == 0.f) {
            taui = 0.f;
            ereg[ii] = alpha;
        } else {
            float h2 = fmaf(alpha, alpha, xn2);
            float beta = -signf_(h2 * frsqrt_(h2), alpha);
            taui = (beta - alpha) * frcp_(beta);
            float sc = frcp_(alpha - beta);
            ereg[ii] = beta;
            __syncwarp(M);                       // all lanes done reading col ii
            if (lane >= ii + 2) A[lane][ii] *= sc;
            if (lane == ii + 1) A[ii + 1][ii] = 1.f;
            __syncwarp(M);
            if (lane >= ii + 1) {
                float s = 0.f;
#pragma unroll
                for (int c2 = ii + 1; c2 < 10; c2++) {
                    float av = (lane >= c2) ? A[lane][c2] : A[c2][lane];
                    s += av * A[c2][ii];
                }
                wsh[lane] = taui * s;
            }
            __syncwarp(M);
            float dot = 0.f;
#pragma unroll
            for (int r2 = ii + 1; r2 < 10; r2++) dot += wsh[r2] * A[r2][ii];
            float alw = -0.5f * taui * dot;
            __syncwarp(M);
            if (lane >= ii + 1) wsh[lane] += alw * A[lane][ii];
            __syncwarp(M);
            if (lane >= ii + 1) {
                for (int c2 = ii + 1; c2 <= lane; c2++)
                    A[lane][c2] -= A[lane][ii] * wsh[c2] + wsh[lane] * A[c2][ii];
            }
            __syncwarp(M);
            if (lane == ii + 1) A[ii + 1][ii] = ereg[ii];
        }
        taul[ii] = taui;
    }
    __syncwarp(M);
#pragma unroll
    for (int k = 0; k < 10; k++) dreg[k] = A[k][k];

    // =======================================================================
    // Q = H(1)..H(n-1): lane j owns column j.
    // =======================================================================
    float qc[10];
#pragma unroll
    for (int r2 = 0; r2 < 10; r2++) qc[r2] = (r2 == lane) ? 1.f : 0.f;
#pragma unroll
    for (int ii = 8; ii >= 0; ii--) {
        float taui = taul[ii];
        if (taui != 0.f) {
            float s = 0.f;
#pragma unroll
            for (int r2 = 0; r2 < 10; r2++) {
                if (r2 == ii + 1)      s += qc[r2];
                else if (r2 >= ii + 2) s += A[r2][ii] * qc[r2];
            }
            s *= taui;
#pragma unroll
            for (int r2 = 0; r2 < 10; r2++) {
                if (r2 == ii + 1)      qc[r2] -= s;
                else if (r2 >= ii + 2) qc[r2] -= A[r2][ii] * s;
            }
        }
    }
#pragma unroll
    for (int r2 = 0; r2 < 10; r2++) Zsh[r2][lane] = qc[r2];
    __syncwarp(M);
    float z[10];
#pragma unroll
    for (int c2 = 0; c2 < 10; c2++) z[c2] = Zsh[lane][c2];

    // =======================================================================
    // ssteqr ('V'), register-resident, approx arithmetic, LAPACK structure.
    // =======================================================================
    {
    const float EPS    = 5.9604645e-08f;
    const float EPS2   = EPS * EPS;
    const float SAFMIN = 1.1754944e-38f;
    int n = 10, nmaxit = n * 30, jtot = 0;
    int l1 = 1, l = 0, lsv, lend, lendsv, m;
    float p, g, r, c, s, f, b, rt1, rt2;

L10:
    if (l1 > n) goto L160;
    if (l1 > 1) rset10(ereg, l1 - 1, 0.f);
    if (l1 <= n - 1) {
        int msel = n; bool fnd = false;
#pragma unroll
        for (int mm = 1; mm <= 9; mm++) {
            if (!fnd && mm >= l1) {
                float tst = fabsf(ereg[mm - 1]);
                if (tst == 0.f) { msel = mm; fnd = true; }
                else {
                    float prod = fabsf(dreg[mm - 1]) * fabsf(dreg[mm]);
                    if (tst <= fsqrt_(prod) * EPS) {
                        ereg[mm - 1] = 0.f; msel = mm; fnd = true;
                    }
                }
            }
        }
        m = msel;
    } else m = n;
// L30:
    l = l1; lsv = l; lend = m; lendsv = lend; l1 = m + 1;
    if (lend == l) goto L10;
    if (fabsf(rget10(dreg, lend)) < fabsf(rget10(dreg, l))) { lend = lsv; l = lendsv; }
    if (lend > l) goto L40; else goto L90;

    // ============ QL iteration ============
L40:
    if (l != lend) {
        int msel = lend; bool fnd = false;
#pragma unroll
        for (int mm = 1; mm <= 9; mm++) {
            if (!fnd && mm >= l && mm <= lend - 1) {
                float tst = ereg[mm - 1] * ereg[mm - 1];
                if (tst <= EPS2 * fabsf(dreg[mm - 1]) * fabsf(dreg[mm]) + SAFMIN) {
                    msel = mm; fnd = true;
                }
            }
        }
        m = msel;
    } else m = lend;
    if (m < lend) rset10(ereg, m, 0.f);
    p = rget10(dreg, l);
    if (m == l) goto L80;
    if (m == l + 1) {
        slaev2_(rget10(dreg, l), rget10(ereg, l), rget10(dreg, l + 1), &rt1, &rt2, &c, &s);
#pragma unroll
        for (int jj = 0; jj < 9; jj++) if (jj == l - 1) {
            float tmp = z[jj + 1];
            z[jj + 1] = c * tmp - s * z[jj];
            z[jj]     = s * tmp + c * z[jj];
        }
        rset10(dreg, l, rt1); rset10(dreg, l + 1, rt2); rset10(ereg, l, 0.f);
        l += 2;
        if (l <= lend) goto L40;
        goto L140;
    }
    if (jtot == nmaxit) goto L140;
    jtot++;
    {
        float el = rget10(ereg, l);
        g = (rget10(dreg, l + 1) - p) * (0.5f * frcp_(el));
        r = slapy2_1_(g);
        g = rget10(dreg, m) - p + el * frcp_(g + signf_(r, g));
    }
    s = 1.f; c = 1.f; p = 0.f;
#pragma unroll
    for (int i = 9; i >= 1; i--) {
        if (i <= m - 1 && i >= l) {
            f = s * ereg[i - 1]; b = c * ereg[i - 1];
            slartg_(g, f, &c, &s, &r);
            if (i != m - 1) ereg[i] = r;
            g = dreg[i] - p;
            r = (dreg[i - 1] - g) * s + 2.f * c * b;
            p = s * r;
            dreg[i] = g + p;
            g = c * r - b;
            wcr[i - 1] = c; wsr[i - 1] = -s;
        }
    }
#pragma unroll
    for (int jj = 8; jj >= 0; jj--) {
        if (jj >= l - 1 && jj <= m - 2) {
            float ct = wcr[jj], st = wsr[jj];
            float tmp = z[jj + 1];
            z[jj + 1] = ct * tmp - st * z[jj];
            z[jj]     = st * tmp + ct * z[jj];
        }
    }
    rset10(dreg, l, rget10(dreg, l) - p);
    rset10(ereg, l, g);
    goto L40;
L80:
    rset10(dreg, l, p);
    l++;
    if (l <= lend) goto L40;
    goto L140;

    // ============ QR iteration ============
L90:
    if (l != lend) {
        int msel = lend; bool fnd = false;
#pragma unroll
        for (int mm = 10; mm >= 2; mm--) {
            if (!fnd && mm <= l && mm >= lend + 1) {
                float tst = ereg[mm - 2] * ereg[mm - 2];
                if (tst <= EPS2 * fabsf(dreg[mm - 1]) * fabsf(dreg[mm - 2]) + SAFMIN) {
                    msel = mm; fnd = true;
                }
            }
        }
        m = msel;
    } else m = lend;
    if (m > lend) rset10(ereg, m - 1, 0.f);
    p = rget10(dreg, l);
    if (m == l) goto L130;
    if (m == l - 1) {
        slaev2_(rget10(dreg, l - 1), rget10(ereg, l - 1), rget10(dreg, l), &rt1, &rt2, &c, &s);
#pragma unroll
        for (int jj = 0; jj < 9; jj++) if (jj == l - 2) {
            float tmp = z[jj + 1];
            z[jj + 1] = c * tmp - s * z[jj];
            z[jj]     = s * tmp + c * z[jj];
        }
        rset10(dreg, l - 1, rt1); rset10(dreg, l, rt2); rset10(ereg, l - 1, 0.f);
        l -= 2;
        if (l >= lend) goto L90;
        goto L140;
    }
    if (jtot == nmaxit) goto L140;
    jtot++;
    {
        float el = rget10(ereg, l - 1);
        g = (rget10(dreg, l - 1) - p) * (0.5f * frcp_(el));
        r = slapy2_1_(g);
        g = rget10(dreg, m) - p + el * frcp_(g + signf_(r, g));
    }
    s = 1.f; c = 1.f; p = 0.f;
#pragma unroll
    for (int i = 1; i <= 9; i++) {
        if (i >= m && i <= l - 1) {
            f = s * ereg[i - 1]; b = c * ereg[i - 1];
            slartg_(g, f, &c, &s, &r);
            if (i >= 2) { if (i != m) ereg[i - 2] = r; }
            g = dreg[i - 1] - p;
            r = (dreg[i] - g) * s + 2.f * c * b;
            p = s * r;
            dreg[i - 1] = g + p;
            g = c * r - b;
            wcr[i - 1] = c; wsr[i - 1] = s;
        }
    }
#pragma unroll
    for (int jj = 0; jj <= 8; jj++) {
        if (jj >= m - 1 && jj <= l - 2) {
            float ct = wcr[jj], st = wsr[jj];
            float tmp = z[jj + 1];
            z[jj + 1] = ct * tmp - st * z[jj];
            z[jj]     = st * tmp + ct * z[jj];
        }
    }
    rset10(dreg, l, rget10(dreg, l) - p);
    rset10(ereg, l - 1, g);
    goto L90;
L130:
    rset10(dreg, l, p);
    l--;
    if (l >= lend) goto L90;
    goto L140;

L140:
    if (jtot < nmaxit) goto L10;
    goto L160;

L160:
    // LAPACK ascending selection sort with column swaps.
    for (int ii2 = 2; ii2 <= n; ii2++) {
        int i = ii2 - 1, k = i;
        float pp = rget10(dreg, i);
#pragma unroll
        for (int j = 2; j <= 10; j++) {
            if (j >= ii2) {
                float dj = dreg[j - 1];
                if (dj < pp) { k = j; pp = dj; }
            }
        }
        if (k != i) {
            rset10(dreg, k, rget10(dreg, i));
            rset10(dreg, i, pp);
            float zi = 0.f, zk = 0.f;
#pragma unroll
            for (int cidx = 0; cidx < 10; cidx++) {
                if (cidx == i - 1) zi = z[cidx];
                if (cidx == k - 1) zk = z[cidx];
            }
#pragma unroll
            for (int cidx = 0; cidx < 10; cidx++) {
                if (cidx == i - 1) z[cidx] = zk;
                if (cidx == k - 1) z[cidx] = zi;
            }
        }
    }
    }

    // ---- MLP per-lane: lane i computes output row i ------------------------
    {
        float y2 = sb2[0];
#pragma unroll
        for (int h = 0; h < 16; h++) {
            float a1 = sb1[h];
#pragma unroll
            for (int j = 0; j < 10; j++) a1 = fmaf(z[j], sW1[h * 10 + j], a1);
            a1 = fmaxf(a1, 0.f);
            y2 = fmaf(a1, sW2[h], y2);
        }
        out[lane] = 0.5f * (1.f / (1.f + expf(-y2)) + 1.f);
    }
}

extern "C" void kernel_launch(void* const* d_in, const int* in_sizes, int n_in,
                              void* d_out, int out_size)
{
    const float* x  = (const float*)d_in[0];
    const float* W1 = (const float*)d_in[1];
    const float* b1 = (const float*)d_in[2];
    const float* W2 = (const float*)d_in[3];
    const float* b2 = (const float*)d_in[4];
    int nrows = in_sizes[0] / 10;
    int quads = nrows / 4;
    gram_kernel<<<NBLK, TPB>>>(x, quads, nrows);
    reduce_kernel<<<55, 256>>>();
    finish_kernel<<<1, 32>>>(W1, b1, W2, b2, (float*)d_out);
}

// round 9
// speedup vs baseline: 2.9005x; 1.0817x over previous
#include <cuda_runtime.h>
#include <math.h>

#define NBLK 592          // 4 CTAs x 148 SMs = exactly one wave
#define TPB  128
#define NWARP (NBLK * 4)

// Per-block partials, entry-major for coalesced reduction.
__device__ float g_part_T[55][NBLK];
__device__ float g_gram[55];

__device__ __forceinline__ constexpr int tri_idx(int i, int j) {
    return i * 10 - (i * (i + 1)) / 2 + j;   // i <= j
}

// ---------------------------------------------------------------------------
// Kernel 1: Gram partial reduction with warp-cooperative smem staging.
// Unit = 128 rows (5120B) per warp:
//   - 10 coalesced LDG.128 per lane (stride 32)  -> 4 lines/warp-load
//   - stage to warp-private smem buffer
//   - each lane reads its 4 contiguous rows back (LDS.128) and accumulates
// ---------------------------------------------------------------------------
__global__ __launch_bounds__(TPB, 4) void gram_kernel(const float* __restrict__ x,
                                                      int units, int nrows)
{
    __shared__ float4 buf[4][320];          // 5120B per warp
    const float4* __restrict__ xv = (const float4*)x;

    float acc[55];
#pragma unroll
    for (int k = 0; k < 55; k++) acc[k] = 0.f;

    int warp = threadIdx.x >> 5, lane = threadIdx.x & 31;
    int gw = blockIdx.x * 4 + warp;
    float4* wbuf = buf[warp];

    for (int u = gw; u < units; u += NWARP) {
        const float4* __restrict__ src = xv + (size_t)u * 320;
        // Coalesced fill: lane-stride-32, 10 independent 128-bit loads.
#pragma unroll
        for (int k = 0; k < 10; k++)
            wbuf[lane + 32 * k] = src[lane + 32 * k];
        __syncwarp();
        // Read back 4 contiguous rows (40 floats = 10 float4) per lane.
        float v[40];
#pragma unroll
        for (int i = 0; i < 10; i++) {
            float4 q = wbuf[10 * lane + i];
            v[4 * i + 0] = q.x; v[4 * i + 1] = q.y;
            v[4 * i + 2] = q.z; v[4 * i + 3] = q.w;
        }
#pragma unroll
        for (int r = 0; r < 4; r++)
#pragma unroll
            for (int i = 0; i < 10; i++)
#pragma unroll
                for (int j = i; j < 10; j++)
                    acc[tri_idx(i, j)] =
                        fmaf(v[10 * r + i], v[10 * r + j], acc[tri_idx(i, j)]);
        __syncwarp();                        // readers done before next fill
    }

    // Tail rows (nrows % 128), scalar on one thread (not hit for N=4M).
    if (blockIdx.x == 0 && threadIdx.x == 0) {
        for (int rr = 128 * units; rr < nrows; rr++) {
            const float* row = x + (size_t)rr * 10;
            float v[10];
#pragma unroll
            for (int i = 0; i < 10; i++) v[i] = row[i];
#pragma unroll
            for (int i = 0; i < 10; i++)
#pragma unroll
                for (int j = i; j < 10; j++)
                    acc[tri_idx(i, j)] = fmaf(v[i], v[j], acc[tri_idx(i, j)]);
        }
    }

    // Deterministic warp shuffle tree reduce per entry.
#pragma unroll
    for (int k = 0; k < 55; k++) {
#pragma unroll
        for (int off = 16; off > 0; off >>= 1)
            acc[k] += __shfl_down_sync(0xffffffffu, acc[k], off);
    }
    __shared__ float red[TPB / 32][55];
    if (lane == 0) {
#pragma unroll
        for (int k = 0; k < 55; k++) red[warp][k] = acc[k];
    }
    __syncthreads();
    if (threadIdx.x < 55) {
        float s = 0.f;
#pragma unroll
        for (int w = 0; w < TPB / 32; w++) s += red[w][threadIdx.x];
        g_part_T[threadIdx.x][blockIdx.x] = s;
    }
}

// ---------------------------------------------------------------------------
// Kernel 2: per-entry coalesced deterministic reduction.
// ---------------------------------------------------------------------------
__global__ __launch_bounds__(256, 1) void reduce_kernel()
{
    __shared__ double sh[256];
    int e = blockIdx.x, q = threadIdx.x;
    double s = 0.0;
    for (int k = q; k < NBLK; k += 256)
        s += (double)g_part_T[e][k];
    sh[q] = s;
    __syncthreads();
#pragma unroll
    for (int off = 128; off > 0; off >>= 1) {
        if (q < off) sh[q] += sh[q + off];
        __syncthreads();
    }
    if (q == 0) g_gram[e] = (float)sh[0];
}

// ---------------------------------------------------------------------------
// Fast approx primitives (MUFU; <=2^-23 rel err).
// ---------------------------------------------------------------------------
__device__ __forceinline__ float frcp_(float x) {
    float r; asm("rcp.approx.ftz.f32 %0, %1;" : "=f"(r) : "f"(x)); return r;
}
__device__ __forceinline__ float frsqrt_(float x) {
    float r; asm("rsqrt.approx.ftz.f32 %0, %1;" : "=f"(r) : "f"(x)); return r;
}
__device__ __forceinline__ float fsqrt_(float x) {          // x >= 0
    return (x > 0.f) ? x * frsqrt_(x) : 0.f;
}

__device__ __forceinline__ float signf_(float a, float b) {
    return b >= 0.f ? fabsf(a) : -fabsf(a);
}
__device__ __forceinline__ float slapy2_1_(float g) {
    float t = fmaf(g, g, 1.f);
    return t * frsqrt_(t);
}
// Branchless Givens (LAPACK sign convention), rsqrt-based.
__device__ __forceinline__ void slartg_(float f, float g, float* cs, float* sn, float* r) {
    float f2   = fmaf(f, f, g * g);
    float rinv = frsqrt_(f2);
    float d    = f2 * rinv;
    float sgn  = (f >= 0.f) ? 1.f : -1.f;
    float cs0  = fabsf(f) * rinv;
    float sn0  = g * rinv * sgn;
    float r0   = sgn * d;
    bool gz = (g == 0.f), fz = (f == 0.f);
    *cs = gz ? 1.f : (fz ? 0.f                      : cs0);
    *sn = gz ? 0.f : (fz ? ((g >= 0.f) ? 1.f : -1.f): sn0);
    *r  = gz ? f   : (fz ? fabsf(g)                 : r0);
}
__device__ __forceinline__ void slaev2_(float a, float b, float cc,
                        float* rt1, float* rt2, float* cs1o, float* sn1o) {
    float sm = a + cc, df = a - cc;
    float adf = fabsf(df), tb = b + b, ab = fabsf(tb);
    float acmx, acmn;
    if (fabsf(a) > fabsf(cc)) { acmx = a;  acmn = cc; }
    else                      { acmx = cc; acmn = a;  }
    float rt;
    if (adf > ab)      { float t = ab * frcp_(adf); float h = fmaf(t, t, 1.f); rt = adf * (h * frsqrt_(h)); }
    else if (adf < ab) { float t = adf * frcp_(ab); float h = fmaf(t, t, 1.f); rt = ab  * (h * frsqrt_(h)); }
    else               rt = ab * 1.41421356237309515f;
    int sgn1;
    if (sm < 0.f)      { *rt1 = 0.5f * (sm - rt); sgn1 = -1;
                         float ri = frcp_(*rt1);
                         *rt2 = (acmx * ri) * acmn - (b * ri) * b; }
    else if (sm > 0.f) { *rt1 = 0.5f * (sm + rt); sgn1 = 1;
                         float ri = frcp_(*rt1);
                         *rt2 = (acmx * ri) * acmn - (b * ri) * b; }
    else               { *rt1 = 0.5f * rt; *rt2 = -0.5f * rt; sgn1 = 1; }
    float cs; int sgn2;
    if (df >= 0.f) { cs = df + rt; sgn2 = 1; }
    else           { cs = df - rt; sgn2 = -1; }
    float acs = fabsf(cs), c1, s1;
    if (acs > ab) { float ct = -tb * frcp_(cs); s1 = frsqrt_(fmaf(ct, ct, 1.f)); c1 = ct * s1; }
    else {
        if (ab == 0.f) { c1 = 1.f; s1 = 0.f; }
        else { float tn = -cs * frcp_(tb); c1 = frsqrt_(fmaf(tn, tn, 1.f)); s1 = tn * c1; }
    }
    if (sgn1 == sgn2) { float t = c1; c1 = -s1; s1 = t; }
    *cs1o = c1; *sn1o = s1;
}

// Predicated register-array access (1-based index); keeps arrays in registers.
__device__ __forceinline__ float rget10(const float (&a)[10], int k1) {
    float v = a[0];
#pragma unroll
    for (int k = 2; k <= 10; k++) if (k1 == k) v = a[k - 1];
    return v;
}
__device__ __forceinline__ void rset10(float (&a)[10], int k1, float v) {
#pragma unroll
    for (int k = 1; k <= 10; k++) if (k1 == k) a[k - 1] = v;
}

// ---------------------------------------------------------------------------
// Kernel 3 (one warp): gram -> register-resident eigensolver -> MLP.
// ---------------------------------------------------------------------------
__global__ __launch_bounds__(32, 1)
void finish_kernel(const float* __restrict__ W1, const float* __restrict__ b1,
                   const float* __restrict__ W2, const float* __restrict__ b2,
                   float* __restrict__ out)
{
    __shared__ float A[10][10];
    __shared__ float Zsh[10][10];
    __shared__ float wsh[10];
    __shared__ float sW1[160], sb1[16], sW2[16], sb2[1];

    int lane = threadIdx.x;

    // ---- preload weights + gram (one warp, strided) ----
    for (int idx = lane; idx < 160; idx += 32) sW1[idx] = W1[idx];
    if (lane < 16) { sb1[lane] = b1[lane]; sW2[lane] = W2[lane]; }
    if (lane == 0) sb2[0] = b2[0];
    for (int idx = lane; idx < 55; idx += 32) {
        int i = 0, rem = idx;
        while (rem >= 10 - i) { rem -= 10 - i; i++; }
        int j = i + rem;
        float fv = g_gram[idx];
        A[i][j] = fv; A[j][i] = fv;
    }
    __syncwarp();
    const unsigned M = 0x3ffu;
    if (lane >= 10) return;

    // =======================================================================
    // ssytd2 (UPLO='L'), lane-parallel; approx div/sqrt.
    // =======================================================================
    float dreg[10], ereg[10], wcr[10], wsr[10], taul[9];
#pragma unroll
    for (int ii = 0; ii < 9; ii++) {
        __syncwarp(M);
        float alpha = A[ii + 1][ii];
        float xn2 = 0.f;
#pragma unroll
        for (int r2 = ii + 2; r2 < 10; r2++) xn2 += A[r2][ii] * A[r2][ii];
        float xnorm = fsqrt_(xn2);
        float taui;
        if (xnorm == 0.f) {
            taui = 0.f;
            ereg[ii] = alpha;
        } else {
            float h2 = fmaf(alpha, alpha, xn2);
            float beta = -signf_(h2 * frsqrt_(h2), alpha);
            taui = (beta - alpha) * frcp_(beta);
            float sc = frcp_(alpha - beta);
            ereg[ii] = beta;
            __syncwarp(M);                       // all lanes done reading col ii
            if (lane >= ii + 2) A[lane][ii] *= sc;
            if (lane == ii + 1) A[ii + 1][ii] = 1.f;
            __syncwarp(M);
            if (lane >= ii + 1) {
                float s = 0.f;
#pragma unroll
                for (int c2 = ii + 1; c2 < 10; c2++) {
                    float av = (lane >= c2) ? A[lane][c2] : A[c2][lane];
                    s += av * A[c2][ii];
                }
                wsh[lane] = taui * s;
            }
            __syncwarp(M);
            float dot = 0.f;
#pragma unroll
            for (int r2 = ii + 1; r2 < 10; r2++) dot += wsh[r2] * A[r2][ii];
            float alw = -0.5f * taui * dot;
            __syncwarp(M);
            if (lane >= ii + 1) wsh[lane] += alw * A[lane][ii];
            __syncwarp(M);
            if (lane >= ii + 1) {
                for (int c2 = ii + 1; c2 <= lane; c2++)
                    A[lane][c2] -= A[lane][ii] * wsh[c2] + wsh[lane] * A[c2][ii];
            }
            __syncwarp(M);
            if (lane == ii + 1) A[ii + 1][ii] = ereg[ii];
        }
        taul[ii] = taui;
    }
    __syncwarp(M);
#pragma unroll
    for (int k = 0; k < 10; k++) dreg[k] = A[k][k];

    // =======================================================================
    // Q = H(1)..H(n-1): lane j owns column j.
    // =======================================================================
    float qc[10];
#pragma unroll
    for (int r2 = 0; r2 < 10; r2++) qc[r2] = (r2 == lane) ? 1.f : 0.f;
#pragma unroll
    for (int ii = 8; ii >= 0; ii--) {
        float taui = taul[ii];
        if (taui != 0.f) {
            float s = 0.f;
#pragma unroll
            for (int r2 = 0; r2 < 10; r2++) {
                if (r2 == ii + 1)      s += qc[r2];
                else if (r2 >= ii + 2) s += A[r2][ii] * qc[r2];
            }
            s *= taui;
#pragma unroll
            for (int r2 = 0; r2 < 10; r2++) {
                if (r2 == ii + 1)      qc[r2] -= s;
                else if (r2 >= ii + 2) qc[r2] -= A[r2][ii] * s;
            }
        }
    }
#pragma unroll
    for (int r2 = 0; r2 < 10; r2++) Zsh[r2][lane] = qc[r2];
    __syncwarp(M);
    float z[10];
#pragma unroll
    for (int c2 = 0; c2 < 10; c2++) z[c2] = Zsh[lane][c2];

    // =======================================================================
    // ssteqr ('V'), register-resident, approx arithmetic, LAPACK structure.
    // =======================================================================
    {
    const float EPS    = 5.9604645e-08f;
    const float EPS2   = EPS * EPS;
    const float SAFMIN = 1.1754944e-38f;
    int n = 10, nmaxit = n * 30, jtot = 0;
    int l1 = 1, l = 0, lsv, lend, lendsv, m;
    float p, g, r, c, s, f, b, rt1, rt2;

L10:
    if (l1 > n) goto L160;
    if (l1 > 1) rset10(ereg, l1 - 1, 0.f);
    if (l1 <= n - 1) {
        int msel = n; bool fnd = false;
#pragma unroll
        for (int mm = 1; mm <= 9; mm++) {
            if (!fnd && mm >= l1) {
                float tst = fabsf(ereg[mm - 1]);
                if (tst == 0.f) { msel = mm; fnd = true; }
                else {
                    float prod = fabsf(dreg[mm - 1]) * fabsf(dreg[mm]);
                    if (tst <= fsqrt_(prod) * EPS) {
                        ereg[mm - 1] = 0.f; msel = mm; fnd = true;
                    }
                }
            }
        }
        m = msel;
    } else m = n;
// L30:
    l = l1; lsv = l; lend = m; lendsv = lend; l1 = m + 1;
    if (lend == l) goto L10;
    if (fabsf(rget10(dreg, lend)) < fabsf(rget10(dreg, l))) { lend = lsv; l = lendsv; }
    if (lend > l) goto L40; else goto L90;

    // ============ QL iteration ============
L40:
    if (l != lend) {
        int msel = lend; bool fnd = false;
#pragma unroll
        for (int mm = 1; mm <= 9; mm++) {
            if (!fnd && mm >= l && mm <= lend - 1) {
                float tst = ereg[mm - 1] * ereg[mm - 1];
                if (tst <= EPS2 * fabsf(dreg[mm - 1]) * fabsf(dreg[mm]) + SAFMIN) {
                    msel = mm; fnd = true;
                }
            }
        }
        m = msel;
    } else m = lend;
    if (m < lend) rset10(ereg, m, 0.f);
    p = rget10(dreg, l);
    if (m == l) goto L80;
    if (m == l + 1) {
        slaev2_(rget10(dreg, l), rget10(ereg, l), rget10(dreg, l + 1), &rt1, &rt2, &c, &s);
#pragma unroll
        for (int jj = 0; jj < 9; jj++) if (jj == l - 1) {
            float tmp = z[jj + 1];
            z[jj + 1] = c * tmp - s * z[jj];
            z[jj]     = s * tmp + c * z[jj];
        }
        rset10(dreg, l, rt1); rset10(dreg, l + 1, rt2); rset10(ereg, l, 0.f);
        l += 2;
        if (l <= lend) goto L40;
        goto L140;
    }
    if (jtot == nmaxit) goto L140;
    jtot++;
    {
        float el = rget10(ereg, l);
        g = (rget10(dreg, l + 1) - p) * (0.5f * frcp_(el));
        r = slapy2_1_(g);
        g = rget10(dreg, m) - p + el * frcp_(g + signf_(r, g));
    }
    s = 1.f; c = 1.f; p = 0.f;
#pragma unroll
    for (int i = 9; i >= 1; i--) {
        if (i <= m - 1 && i >= l) {
            f = s * ereg[i - 1]; b = c * ereg[i - 1];
            slartg_(g, f, &c, &s, &r);
            if (i != m - 1) ereg[i] = r;
            g = dreg[i] - p;
            r = (dreg[i - 1] - g) * s + 2.f * c * b;
            p = s * r;
            dreg[i] = g + p;
            g = c * r - b;
            wcr[i - 1] = c; wsr[i - 1] = -s;
        }
    }
#pragma unroll
    for (int jj = 8; jj >= 0; jj--) {
        if (jj >= l - 1 && jj <= m - 2) {
            float ct = wcr[jj], st = wsr[jj];
            float tmp = z[jj + 1];
            z[jj + 1] = ct * tmp - st * z[jj];
            z[jj]     = st * tmp + ct * z[jj];
        }
    }
    rset10(dreg, l, rget10(dreg, l) - p);
    rset10(ereg, l, g);
    goto L40;
L80:
    rset10(dreg, l, p);
    l++;
    if (l <= lend) goto L40;
    goto L140;

    // ============ QR iteration ============
L90:
    if (l != lend) {
        int msel = lend; bool fnd = false;
#pragma unroll
        for (int mm = 10; mm >= 2; mm--) {
            if (!fnd && mm <= l && mm >= lend + 1) {
                float tst = ereg[mm - 2] * ereg[mm - 2];
                if (tst <= EPS2 * fabsf(dreg[mm - 1]) * fabsf(dreg[mm - 2]) + SAFMIN) {
                    msel = mm; fnd = true;
                }
            }
        }
        m = msel;
    } else m = lend;
    if (m > lend) rset10(ereg, m - 1, 0.f);
    p = rget10(dreg, l);
    if (m == l) goto L130;
    if (m == l - 1) {
        slaev2_(rget10(dreg, l - 1), rget10(ereg, l - 1), rget10(dreg, l), &rt1, &rt2, &c, &s);
#pragma unroll
        for (int jj = 0; jj < 9; jj++) if (jj == l - 2) {
            float tmp = z[jj + 1];
            z[jj + 1] = c * tmp - s * z[jj];
            z[jj]     = s * tmp + c * z[jj];
        }
        rset10(dreg, l - 1, rt1); rset10(dreg, l, rt2); rset10(ereg, l - 1, 0.f);
        l -= 2;
        if (l >= lend) goto L90;
        goto L140;
    }
    if (jtot == nmaxit) goto L140;
    jtot++;
    {
        float el = rget10(ereg, l - 1);
        g = (rget10(dreg, l - 1) - p) * (0.5f * frcp_(el));
        r = slapy2_1_(g);
        g = rget10(dreg, m) - p + el * frcp_(g + signf_(r, g));
    }
    s = 1.f; c = 1.f; p = 0.f;
#pragma unroll
    for (int i = 1; i <= 9; i++) {
        if (i >= m && i <= l - 1) {
            f = s * ereg[i - 1]; b = c * ereg[i - 1];
            slartg_(g, f, &c, &s, &r);
            if (i >= 2) { if (i != m) ereg[i - 2] = r; }
            g = dreg[i - 1] - p;
            r = (dreg[i] - g) * s + 2.f * c * b;
            p = s * r;
            dreg[i - 1] = g + p;
            g = c * r - b;
            wcr[i - 1] = c; wsr[i - 1] = s;
        }
    }
#pragma unroll
    for (int jj = 0; jj <= 8; jj++) {
        if (jj >= m - 1 && jj <= l - 2) {
            float ct = wcr[jj], st = wsr[jj];
            float tmp = z[jj + 1];
            z[jj + 1] = ct * tmp - st * z[jj];
            z[jj]     = st * tmp + ct * z[jj];
        }
    }
    rset10(dreg, l, rget10(dreg, l) - p);
    rset10(ereg, l - 1, g);
    goto L90;
L130:
    rset10(dreg, l, p);
    l--;
    if (l >= lend) goto L90;
    goto L140;

L140:
    if (jtot < nmaxit) goto L10;
    goto L160;

L160:
    // LAPACK ascending selection sort with column swaps.
    for (int ii2 = 2; ii2 <= n; ii2++) {
        int i = ii2 - 1, k = i;
        float pp = rget10(dreg, i);
#pragma unroll
        for (int j = 2; j <= 10; j++) {
            if (j >= ii2) {
                float dj = dreg[j - 1];
                if (dj < pp) { k = j; pp = dj; }
            }
        }
        if (k != i) {
            rset10(dreg, k, rget10(dreg, i));
            rset10(dreg, i, pp);
            float zi = 0.f, zk = 0.f;
#pragma unroll
            for (int cidx = 0; cidx < 10; cidx++) {
                if (cidx == i - 1) zi = z[cidx];
                if (cidx == k - 1) zk = z[cidx];
            }
#pragma unroll
            for (int cidx = 0; cidx < 10; cidx++) {
                if (cidx == i - 1) z[cidx] = zk;
                if (cidx == k - 1) z[cidx] = zi;
            }
        }
    }
    }

    // ---- MLP per-lane: lane i computes output row i ------------------------
    {
        float y2 = sb2[0];
#pragma unroll
        for (int h = 0; h < 16; h++) {
            float a1 = sb1[h];
#pragma unroll
            for (int j = 0; j < 10; j++) a1 = fmaf(z[j], sW1[h * 10 + j], a1);
            a1 = fmaxf(a1, 0.f);
            y2 = fmaf(a1, sW2[h], y2);
        }
        out[lane] = 0.5f * (1.f / (1.f + expf(-y2)) + 1.f);
    }
}

extern "C" void kernel_launch(void* const* d_in, const int* in_sizes, int n_in,
                              void* d_out, int out_size)
{
    const float* x  = (const float*)d_in[0];
    const float* W1 = (const float*)d_in[1];
    const float* b1 = (const float*)d_in[2];
    const float* W2 = (const float*)d_in[3];
    const float* b2 = (const float*)d_in[4];
    int nrows = in_sizes[0] / 10;
    int units = nrows / 128;                 // 128-row units per warp
    gram_kernel<<<NBLK, TPB>>>(x, units, nrows);
    reduce_kernel<<<55, 256>>>();
    finish_kernel<<<1, 32>>>(W1, b1, W2, b2, (float*)d_out);
}